// round 15
// baseline (speedup 1.0000x reference)
#include <cuda_runtime.h>
#include <cuda_bf16.h>
#include <mma.h>
#include <cstdint>

using namespace nvcuda;

constexpr int NB  = 8;
constexpr int NS  = 4096;
constexpr int ND  = 512;
constexpr int NH  = 4;
constexpr int DH  = 64;
constexpr int NI  = 256;
constexpr int NM  = 256;
constexpr int NBH = 32;
constexpr int KW  = 33;
constexpr int SPL = 4;

typedef __nv_bfloat16 bf16;

// ---------------- scratch ----------------------------------------------------
__device__ float g_ohf[(size_t)NB*NS*NI];
__device__ float g_w3p[(size_t)SPL*NBH*NM*DH];
__device__ float g_rs [NBH*NM];
__device__ unsigned g_red[2];

__device__ bf16 g_xnb [(size_t)NB*NS*ND];
__device__ bf16 g_wqkvT[768*512];
__device__ bf16 g_woutT[512*256];
__device__ bf16 g_qb  [(size_t)NBH*NS*DH];
__device__ bf16 g_kb  [(size_t)NBH*NS*DH];
__device__ bf16 g_vb  [(size_t)NBH*NS*DH];
__device__ bf16 g_vT  [(size_t)NBH*DH*NS];
__device__ bf16 g_qlb [NBH*NM*DH];
__device__ bf16 g_klb [NBH*NM*DH];
__device__ bf16 g_a1b [(size_t)NBH*NS*NM];
__device__ bf16 g_a2b [NBH*NM*NM];
__device__ bf16 g_a3b [(size_t)NBH*NM*NS];   // exp(scores), unnormalized
__device__ bf16 g_zA  [NBH*NM*NM];
__device__ bf16 g_zAT [NBH*NM*NM];
__device__ bf16 g_zB  [NBH*NM*NM];
__device__ bf16 g_zBT [NBH*NM*NM];
__device__ bf16 g_xz  [NBH*NM*NM];
__device__ bf16 g_xzT [NBH*NM*NM];
__device__ bf16 g_t1T [NBH*NM*NM];
__device__ bf16 g_t2T [NBH*NM*NM];
__device__ bf16 g_w3T [NBH*DH*NM];
__device__ bf16 g_uT  [NBH*DH*NM];
__device__ bf16 g_ohb [(size_t)NB*NS*NI];

__device__ __forceinline__ uint32_t pack_bf2(float a, float b) {
    __nv_bfloat162 h = __floats2bfloat162_rn(a, b);
    return *reinterpret_cast<uint32_t*>(&h);
}
__device__ __forceinline__ uint32_t smem_u32(const void* p) {
    uint32_t a;
    asm("{ .reg .u64 t; cvta.to.shared.u64 t, %1; cvt.u32.u64 %0, t; }" : "=r"(a) : "l"(p));
    return a;
}
__device__ __forceinline__ void cp16(void* dst, const void* src) {
    asm volatile("cp.async.cg.shared.global [%0], [%1], 16;"
                 :: "r"(smem_u32(dst)), "l"(src) : "memory");
}
__device__ __forceinline__ void cp_commit() { asm volatile("cp.async.commit_group;" ::: "memory"); }
__device__ __forceinline__ void cp_wait0()  { asm volatile("cp.async.wait_group 0;" ::: "memory"); }
__device__ __forceinline__ void cp_wait1()  { asm volatile("cp.async.wait_group 1;" ::: "memory"); }

// ============================================================================
// wmma bf16 GEMM: 256 thr / 8 warps, block 128xBN, warp 32x(BN/2), BK=32,
// cp.async 2-stage. D = A[M,K] @ BT[N,K]^T, fp32 accum, fused epilogues.
// ============================================================================
constexpr int LDT = 40;

template <int BN>
__global__ __launch_bounds__(256, 2) void gemm_wmma(
    const bf16* __restrict__ A, const bf16* __restrict__ BT,
    int K, long long sA, long long sB,
    int mode, float aCoef, float sCoef, float scl,
    bf16* outb, bf16* outbT, float* __restrict__ outf,
    const float* __restrict__ bias, const float* __restrict__ xres,
    long long sC, int rsC)
{
    constexpr int NJ   = BN / 32;
    constexpr int LDCS = BN + 4;

    extern __shared__ __align__(32) char smem[];
    bf16* As = reinterpret_cast<bf16*>(smem);
    bf16* Bs = As + 2*128*LDT;
    float* Cs = reinterpret_cast<float*>(smem);

    int tid = threadIdx.x, wid = tid >> 5;
    int bz = blockIdx.z;
    const bf16* Ab = A  + (size_t)bz * sA;
    const bf16* Bb = BT + (size_t)bz * sB;
    int n0 = blockIdx.x * BN, m0 = blockIdx.y * 128;
    int wm = (wid & 3) * 32, wn = (wid >> 2) * (NJ * 16);

    wmma::fragment<wmma::accumulator, 16, 16, 16, float> acc[2][NJ];
#pragma unroll
    for (int i = 0; i < 2; i++)
#pragma unroll
        for (int j = 0; j < NJ; j++) wmma::fill_fragment(acc[i][j], 0.0f);

    int arow = tid >> 2, akc = (tid & 3) << 3;
    int nch = K >> 5;

    auto load_chunk = [&](int st, int k0) {
        bf16* Ad = As + st * 128*LDT;
        bf16* Bd = Bs + st * BN*LDT;
#pragma unroll
        for (int i = 0; i < 2; i++)
            cp16(Ad + (arow + i*64)*LDT + akc,
                 Ab + (size_t)(m0 + arow + i*64)*K + k0 + akc);
#pragma unroll
        for (int i = 0; i < (BN == 128 ? 2 : 1); i++)
            cp16(Bd + (arow + i*64)*LDT + akc,
                 Bb + (size_t)(n0 + arow + i*64)*K + k0 + akc);
        cp_commit();
    };

    load_chunk(0, 0);
    for (int c = 0; c < nch; c++) {
        bool more = (c + 1 < nch);
        if (more) load_chunk((c + 1) & 1, (c + 1) << 5);
        if (more) cp_wait1(); else cp_wait0();
        __syncthreads();
        const bf16* Ar = As + (c & 1) * 128*LDT;
        const bf16* Br = Bs + (c & 1) * BN*LDT;
#pragma unroll
        for (int kk = 0; kk < 32; kk += 16) {
            wmma::fragment<wmma::matrix_a, 16, 16, 16, bf16, wmma::row_major> af[2];
            wmma::fragment<wmma::matrix_b, 16, 16, 16, bf16, wmma::col_major> bfr[NJ];
#pragma unroll
            for (int i = 0; i < 2; i++)
                wmma::load_matrix_sync(af[i], Ar + (wm + i*16)*LDT + kk, LDT);
#pragma unroll
            for (int j = 0; j < NJ; j++)
                wmma::load_matrix_sync(bfr[j], Br + (wn + j*16)*LDT + kk, LDT);
#pragma unroll
            for (int i = 0; i < 2; i++)
#pragma unroll
                for (int j = 0; j < NJ; j++)
                    wmma::mma_sync(acc[i][j], af[i], bfr[j], acc[i][j]);
        }
        __syncthreads();
    }
#pragma unroll
    for (int i = 0; i < 2; i++)
#pragma unroll
        for (int j = 0; j < NJ; j++)
            wmma::store_matrix_sync(Cs + (wm + i*16)*LDCS + wn + j*16, acc[i][j],
                                    LDCS, wmma::mem_row_major);
    __syncthreads();

    int row = tid >> 1, c0 = (tid & 1) * (BN/2);
    int r = m0 + row;
    const float* cp = Cs + row*LDCS + c0;

    if (mode == 0) {                       // QKV scatter -> bf16 q/k/v (+vT)
        int b = r >> 12, n = r & (NS - 1);
#pragma unroll 8
        for (int c = 0; c < BN/2; c++) {
            int col = n0 + c0 + c;
            int part = col >> 8, e = col & 255;
            int h = e >> 6, d = e & 63;
            float v = cp[c];
            size_t hb = (((size_t)b*NH + h)*NS + n)*DH + d;
            if (part == 0) g_qb[hb] = __float2bfloat16(v * 0.125f);
            else if (part == 1) g_kb[hb] = __float2bfloat16(v);
            else {
                bf16 hv = __float2bfloat16(v);
                g_vb[hb] = hv;
                g_vT[(((size_t)b*NH + h)*DH + d)*NS + n] = hv;
            }
        }
    } else if (mode == 1) {                // pinv: scl*(sCoef*acc + aCoef*A)
        size_t ob = (size_t)bz * 65536;
#pragma unroll 8
        for (int c = 0; c < BN/2; c++) {
            int col = n0 + c0 + c;
            float v = sCoef * cp[c];
            if (aCoef != 0.0f) v += aCoef * __bfloat162float(Ab[(size_t)r*K + col]);
            v *= scl;
            bf16 hv = __float2bfloat16(v);
            if (outb)  outb [ob + (size_t)r*256 + col] = hv;
            if (outbT) outbT[ob + (size_t)col*256 + r] = hv;
        }
    } else if (mode == 2) {                // transposed bf16 write (u^T / w3^T)
        size_t ob = (size_t)bz * (DH*NM);
#pragma unroll 8
        for (int c = 0; c < BN/2; c++)
            outbT[ob + (size_t)(n0 + c0 + c)*256 + r] = __float2bfloat16(cp[c]);
    } else if (mode == 3) {                // a1@u + conv residual -> bf16 oh
        int b = bz >> 2, h = bz & 3;
        size_t base = ((size_t)b*NS + r)*NI + h*64 + n0 + c0;
#pragma unroll 8
        for (int c = 0; c < BN/2; c++)
            g_ohb[base + c] = __float2bfloat16(cp[c] + g_ohf[base + c]);
    } else if (mode == 4) {                // proj: out = acc + bias + x
        size_t base = (size_t)r * ND;
#pragma unroll 8
        for (int c = 0; c < BN/2; c++) {
            int col = n0 + c0 + c;
            outf[base + col] = cp[c] + bias[col] + xres[base + col];
        }
    } else {                               // 5: exp(score) -> bf16 (unnormalized a3)
        bf16* op = outb + (size_t)bz*sC + (size_t)r*rsC + n0 + c0;
#pragma unroll 8
        for (int c = 0; c < BN/2; c++)
            op[c] = __float2bfloat16(__expf(cp[c]));
    }
}

constexpr int DSMEM_128 = 128 * (128 + 4) * 4;
constexpr int DSMEM_64  = 128 * (64 + 4) * 4;

// ============================================================================
// gemm_pinv64: BM=64, BN=128, K=256, BK=32 (verified R12/R13 geometry).
// ============================================================================
constexpr int DSMEM_P64 = 64 * 132 * 4;

__global__ __launch_bounds__(256, 2) void gemm_pinv64(
    const bf16* __restrict__ A, const bf16* __restrict__ BT,
    float aCoef, float sCoef, float scl,
    bf16* outb, bf16* outbT)
{
    constexpr int LDCS = 132;
    extern __shared__ __align__(32) char smem[];
    bf16* As = reinterpret_cast<bf16*>(smem);
    bf16* Bs = As + 2*64*LDT;
    float* Cs = reinterpret_cast<float*>(smem);

    int tid = threadIdx.x, wid = tid >> 5;
    int bz = blockIdx.z;
    const bf16* Ab = A  + (size_t)bz * 65536;
    const bf16* Bb = BT + (size_t)bz * 65536;
    int n0 = blockIdx.x * 128, m0 = blockIdx.y * 64;
    int wm = (wid & 1) * 32, wn = (wid >> 1) * 32;

    wmma::fragment<wmma::accumulator, 16, 16, 16, float> acc[2][2];
#pragma unroll
    for (int i = 0; i < 2; i++)
#pragma unroll
        for (int j = 0; j < 2; j++) wmma::fill_fragment(acc[i][j], 0.0f);

    int arow = tid >> 2, akc = (tid & 3) << 3;

    auto load_chunk = [&](int st, int k0) {
        bf16* Ad = As + st * 64*LDT;
        bf16* Bd = Bs + st * 128*LDT;
        cp16(Ad + arow*LDT + akc, Ab + (size_t)(m0 + arow)*256 + k0 + akc);
#pragma unroll
        for (int i = 0; i < 2; i++)
            cp16(Bd + (arow + i*64)*LDT + akc,
                 Bb + (size_t)(n0 + arow + i*64)*256 + k0 + akc);
        cp_commit();
    };

    load_chunk(0, 0);
    for (int c = 0; c < 8; c++) {
        bool more = (c + 1 < 8);
        if (more) load_chunk((c + 1) & 1, (c + 1) << 5);
        if (more) cp_wait1(); else cp_wait0();
        __syncthreads();
        const bf16* Ar = As + (c & 1) * 64*LDT;
        const bf16* Br = Bs + (c & 1) * 128*LDT;
#pragma unroll
        for (int kk = 0; kk < 32; kk += 16) {
            wmma::fragment<wmma::matrix_a, 16, 16, 16, bf16, wmma::row_major> af[2];
            wmma::fragment<wmma::matrix_b, 16, 16, 16, bf16, wmma::col_major> bfr[2];
#pragma unroll
            for (int i = 0; i < 2; i++)
                wmma::load_matrix_sync(af[i], Ar + (wm + i*16)*LDT + kk, LDT);
#pragma unroll
            for (int j = 0; j < 2; j++)
                wmma::load_matrix_sync(bfr[j], Br + (wn + j*16)*LDT + kk, LDT);
#pragma unroll
            for (int i = 0; i < 2; i++)
#pragma unroll
                for (int j = 0; j < 2; j++)
                    wmma::mma_sync(acc[i][j], af[i], bfr[j], acc[i][j]);
        }
        __syncthreads();
    }
#pragma unroll
    for (int i = 0; i < 2; i++)
#pragma unroll
        for (int j = 0; j < 2; j++)
            wmma::store_matrix_sync(Cs + (wm + i*16)*LDCS + wn + j*16, acc[i][j],
                                    LDCS, wmma::mem_row_major);
    __syncthreads();

    int row = tid >> 2, c0 = (tid & 3) * 32;
    int r = m0 + row;
    const float* cp = Cs + row*LDCS + c0;
    size_t ob = (size_t)bz * 65536;
#pragma unroll 8
    for (int c = 0; c < 32; c++) {
        int col = n0 + c0 + c;
        float v = sCoef * cp[c];
        if (aCoef != 0.0f) v += aCoef * __bfloat162float(Ab[(size_t)r*256 + col]);
        v *= scl;
        bf16 hv = __float2bfloat16(v);
        if (outb)  outb [ob + (size_t)r*256 + col] = hv;
        if (outbT) outbT[ob + (size_t)col*256 + r] = hv;
    }
}

// ============================================================================
// gemm_a3v: split-K w3 partials = exp(a3) @ v. Grid (SPL, 2, NBH).
// ============================================================================
__global__ __launch_bounds__(256, 2) void gemm_a3v()
{
    constexpr int LDCS = 68;
    extern __shared__ __align__(32) char smem[];
    bf16* As = reinterpret_cast<bf16*>(smem);
    bf16* Bs = As + 2*128*LDT;
    float* Cs = reinterpret_cast<float*>(smem);

    int tid = threadIdx.x, wid = tid >> 5;
    int bz = blockIdx.z;
    int split = blockIdx.x;
    int koff = split * (NS / SPL);
    int m0 = blockIdx.y * 128;
    const bf16* Ab = g_a3b + (size_t)bz * NM * NS;
    const bf16* Bb = g_vT  + (size_t)bz * DH * NS;
    int wm = (wid & 3) * 32, wn = (wid >> 2) * 32;

    wmma::fragment<wmma::accumulator, 16, 16, 16, float> acc[2][2];
#pragma unroll
    for (int i = 0; i < 2; i++)
#pragma unroll
        for (int j = 0; j < 2; j++) wmma::fill_fragment(acc[i][j], 0.0f);

    int arow = tid >> 2, akc = (tid & 3) << 3;

    auto load_chunk = [&](int st, int k0) {
        bf16* Ad = As + st * 128*LDT;
        bf16* Bd = Bs + st * 64*LDT;
#pragma unroll
        for (int i = 0; i < 2; i++)
            cp16(Ad + (arow + i*64)*LDT + akc,
                 Ab + (size_t)(m0 + arow + i*64)*NS + koff + k0 + akc);
        cp16(Bd + arow*LDT + akc,
             Bb + (size_t)arow*NS + koff + k0 + akc);
        cp_commit();
    };

    const int NCH = (NS / SPL) / 32;
    load_chunk(0, 0);
    for (int c = 0; c < NCH; c++) {
        bool more = (c + 1 < NCH);
        if (more) load_chunk((c + 1) & 1, (c + 1) << 5);
        if (more) cp_wait1(); else cp_wait0();
        __syncthreads();
        const bf16* Ar = As + (c & 1) * 128*LDT;
        const bf16* Br = Bs + (c & 1) * 64*LDT;
#pragma unroll
        for (int kk = 0; kk < 32; kk += 16) {
            wmma::fragment<wmma::matrix_a, 16, 16, 16, bf16, wmma::row_major> af[2];
            wmma::fragment<wmma::matrix_b, 16, 16, 16, bf16, wmma::col_major> bfr[2];
#pragma unroll
            for (int i = 0; i < 2; i++)
                wmma::load_matrix_sync(af[i], Ar + (wm + i*16)*LDT + kk, LDT);
#pragma unroll
            for (int j = 0; j < 2; j++)
                wmma::load_matrix_sync(bfr[j], Br + (wn + j*16)*LDT + kk, LDT);
#pragma unroll
            for (int i = 0; i < 2; i++)
#pragma unroll
                for (int j = 0; j < 2; j++)
                    wmma::mma_sync(acc[i][j], af[i], bfr[j], acc[i][j]);
        }
        __syncthreads();
    }
#pragma unroll
    for (int i = 0; i < 2; i++)
#pragma unroll
        for (int j = 0; j < 2; j++)
            wmma::store_matrix_sync(Cs + (wm + i*16)*LDCS + wn + j*16, acc[i][j],
                                    LDCS, wmma::mem_row_major);
    __syncthreads();

    int row = tid >> 1, c0 = (tid & 1) * 32;
    int r = m0 + row;
    const float* cp = Cs + row*LDCS + c0;
    float* op = g_w3p + (((size_t)split*NBH + bz)*NM + r)*DH + c0;
#pragma unroll 8
    for (int c = 0; c < 32; c++) op[c] = cp[c];
}

constexpr int DSMEM_A3V = 128 * 68 * 4;

// ---------------- row sums of exp (deterministic, 1 warp/row) ------------------
__global__ __launch_bounds__(256) void rowsum_kernel()
{
    int gw = (blockIdx.x * 256 + threadIdx.x) >> 5;
    int lid = threadIdx.x & 31;
    const bf16* p = g_a3b + (size_t)gw * NS;
    float s = 0.f;
#pragma unroll
    for (int i = 0; i < 16; i++) {
        uint4 u = reinterpret_cast<const uint4*>(p)[lid + i*32];
        const __nv_bfloat162* e = reinterpret_cast<const __nv_bfloat162*>(&u);
#pragma unroll
        for (int j = 0; j < 4; j++) {
            float2 f = __bfloat1622float2(e[j]);
            s += f.x + f.y;
        }
    }
#pragma unroll
    for (int o = 16; o > 0; o >>= 1) s += __shfl_xor_sync(~0u, s, o);
    if (lid == 0) g_rs[gw] = s;
}

// ---------------- split-K reduce + normalize -----------------------------------
__global__ void w3red_kernel()
{
    int idx = blockIdx.x * blockDim.x + threadIdx.x;
    int d = idx & 63, m = (idx >> 6) & 255, bh = idx >> 14;
    float s = 0.f;
#pragma unroll
    for (int sp = 0; sp < SPL; sp++)
        s += g_w3p[(((size_t)sp*NBH + bh)*NM + m)*DH + d];
    s /= g_rs[bh*NM + m];
    g_w3T[(size_t)bh*DH*NM + (size_t)d*NM + m] = __float2bfloat16(s);
}

// ============================================================================
// attn_wmma: O = softmax(Q @ KL^T) rows of 256, bf16 out. 64 q-rows/block.
// ============================================================================
constexpr int ALQ = 72;
constexpr int ALS = 260;
constexpr int ATT_DSMEM = 64*ALQ*2 + 256*ALQ*2 + 64*ALS*4;

__global__ __launch_bounds__(256) void attn_wmma(
    const bf16* __restrict__ Q, bf16* __restrict__ O, int Ma)
{
    extern __shared__ __align__(32) char sm[];
    bf16* Qs = reinterpret_cast<bf16*>(sm);
    bf16* Ks = Qs + 64*ALQ;
    float* Ss = reinterpret_cast<float*>(Ks + 256*ALQ);

    int bh = blockIdx.y, r0 = blockIdx.x * 64;
    const bf16* Qb = Q + ((size_t)bh*Ma + r0)*DH;
    const bf16* Kb = g_klb + (size_t)bh*NM*DH;
    int tid = threadIdx.x, wid = tid >> 5;

    for (int i = tid; i < 64*8; i += 256) {
        int row = i >> 3, c8 = (i & 7) * 8;
        *reinterpret_cast<uint4*>(Qs + row*ALQ + c8) =
            *reinterpret_cast<const uint4*>(Qb + (size_t)row*DH + c8);
    }
    for (int i = tid; i < 256*8; i += 256) {
        int row = i >> 3, c8 = (i & 7) * 8;
        *reinterpret_cast<uint4*>(Ks + row*ALQ + c8) =
            *reinterpret_cast<const uint4*>(Kb + (size_t)row*DH + c8);
    }
    __syncthreads();

    int wm = (wid & 3) * 16, wn = (wid >> 2) * 128;
    wmma::fragment<wmma::accumulator, 16, 16, 16, float> acc[8];
#pragma unroll
    for (int j = 0; j < 8; j++) wmma::fill_fragment(acc[j], 0.0f);
#pragma unroll
    for (int kk = 0; kk < 64; kk += 16) {
        wmma::fragment<wmma::matrix_a, 16, 16, 16, bf16, wmma::row_major> af;
        wmma::load_matrix_sync(af, Qs + wm*ALQ + kk, ALQ);
#pragma unroll
        for (int j = 0; j < 8; j++) {
            wmma::fragment<wmma::matrix_b, 16, 16, 16, bf16, wmma::col_major> bfr;
            wmma::load_matrix_sync(bfr, Ks + (wn + j*16)*ALQ + kk, ALQ);
            wmma::mma_sync(acc[j], af, bfr, acc[j]);
        }
    }
#pragma unroll
    for (int j = 0; j < 8; j++)
        wmma::store_matrix_sync(Ss + wm*ALS + wn + j*16, acc[j], ALS, wmma::mem_row_major);
    __syncthreads();

    int row = tid >> 2, q4 = tid & 3;
    float* sp = Ss + row*ALS + q4*64;
    float mx = -1e30f;
#pragma unroll 16
    for (int c = 0; c < 64; c++) mx = fmaxf(mx, sp[c]);
    mx = fmaxf(mx, __shfl_xor_sync(~0u, mx, 1));
    mx = fmaxf(mx, __shfl_xor_sync(~0u, mx, 2));
    float sum = 0.f;
#pragma unroll 16
    for (int c = 0; c < 64; c++) { float e = __expf(sp[c] - mx); sp[c] = e; sum += e; }
    sum += __shfl_xor_sync(~0u, sum, 1);
    sum += __shfl_xor_sync(~0u, sum, 2);
    float inv = 1.0f / sum;
    bf16* Ob = O + ((size_t)bh*Ma + r0 + row)*NM + q4*64;
#pragma unroll
    for (int c = 0; c < 64; c += 4) {
        uint2 o2 = { pack_bf2(sp[c]*inv, sp[c+1]*inv), pack_bf2(sp[c+2]*inv, sp[c+3]*inv) };
        *reinterpret_cast<uint2*>(Ob + c) = o2;
    }
}

// ---------------- LayerNorm -> bf16 -----------------------------------------
__global__ __launch_bounds__(128) void ln_kernel(
    const float* __restrict__ x, const float* __restrict__ g, const float* __restrict__ b)
{
    int row = blockIdx.x, t = threadIdx.x;
    float4 v4 = reinterpret_cast<const float4*>(x + (size_t)row*ND)[t];
    float s = v4.x + v4.y + v4.z + v4.w;
    __shared__ float r1[4], r2[4];
#pragma unroll
    for (int o = 16; o > 0; o >>= 1) s += __shfl_xor_sync(~0u, s, o);
    if ((t & 31) == 0) r1[t >> 5] = s;
    __syncthreads();
    float mu = (r1[0]+r1[1]+r1[2]+r1[3]) * (1.0f/ND);
    float dx = v4.x-mu, dy = v4.y-mu, dz = v4.z-mu, dw = v4.w-mu;
    float ss = dx*dx + dy*dy + dz*dz + dw*dw;
#pragma unroll
    for (int o = 16; o > 0; o >>= 1) ss += __shfl_xor_sync(~0u, ss, o);
    if ((t & 31) == 0) r2[t >> 5] = ss;
    __syncthreads();
    float inv = rsqrtf((r2[0]+r2[1]+r2[2]+r2[3]) * (1.0f/ND) + 1e-5f);
    float4 gv = reinterpret_cast<const float4*>(g)[t];
    float4 bv = reinterpret_cast<const float4*>(b)[t];
    uint2 o2;
    o2.x = pack_bf2(dx*inv*gv.x + bv.x, dy*inv*gv.y + bv.y);
    o2.y = pack_bf2(dz*inv*gv.z + bv.z, dw*inv*gv.w + bv.w);
    reinterpret_cast<uint2*>(g_xnb + (size_t)row*ND)[t] = o2;
}

// ---------------- weight transposes ------------------------------------------
__global__ void wqkvT_kernel(const float* __restrict__ w) {
    int idx = blockIdx.x * blockDim.x + threadIdx.x;
    int k = idx & 511, n = idx >> 9;
    g_wqkvT[idx] = __float2bfloat16(w[(size_t)k*768 + n]);
}
__global__ void woutT_kernel(const float* __restrict__ w) {
    int idx = blockIdx.x * blockDim.x + threadIdx.x;
    int k = idx & 255, n = idx >> 8;
    g_woutT[idx] = __float2bfloat16(w[(size_t)k*512 + n]);
}

// ---------------- landmarks (bf16 in/out, fp32 accum) -------------------------
__global__ void landmark_kernel(const bf16* __restrict__ src, bf16* __restrict__ dst)
{
    int idx = blockIdx.x * blockDim.x + threadIdx.x;
    int d = idx & 63, j = (idx >> 6) & (NM - 1), bh = idx >> 14;
    const bf16* p = src + ((size_t)bh*NS + (size_t)j*16)*DH + d;
    float s = 0.f;
#pragma unroll
    for (int i = 0; i < 16; i++) s += __bfloat162float(p[(size_t)i*DH]);
    dst[idx] = __float2bfloat16(s * (1.0f/16.0f));
}

// ---------------- pinv prep / init -------------------------------------------
__global__ void init_red_kernel() { g_red[0] = 0u; g_red[1] = 0u; }

__global__ void pinv_prep_kernel()
{
    int i = blockIdx.x * blockDim.x + threadIdx.x;
    int bh = i >> 8, r = i & 255;
    const bf16* A = g_a2b + (size_t)bh*NM*NM;
    float rs = 0.f, cs = 0.f;
    for (int j = 0; j < NM; j++) {
        rs += __bfloat162float(A[(size_t)r*NM + j]);
        cs += __bfloat162float(A[(size_t)j*NM + r]);
    }
    atomicMax(&g_red[0], __float_as_uint(rs));
    atomicMax(&g_red[1], __float_as_uint(cs));
}

__global__ void zinit_kernel()
{
    float inv = 1.0f / (__uint_as_float(g_red[0]) * __uint_as_float(g_red[1]));
    int idx = blockIdx.x * blockDim.x + threadIdx.x;
    int j = idx & 255, i = (idx >> 8) & 255, bh = idx >> 16;
    float a = __bfloat162float(g_a2b[idx]) * inv;
    bf16 h = __float2bfloat16(a);
    g_zAT[idx] = h;
    g_zA[((size_t)bh*NM + j)*NM + i] = h;
}

// ---------------- conv (bf16 v in, fp32 out) ----------------------------------
__global__ __launch_bounds__(256) void conv_kernel(const float* __restrict__ w)
{
    __shared__ float vs[160][64];
    __shared__ float ws[KW];
    int bh = blockIdx.y, n0 = blockIdx.x * 128;
    int b = bh >> 2, h = bh & 3;
    int tid = threadIdx.x;
    const bf16* vb = g_vb + (size_t)bh*NS*DH;
    if (tid < KW) ws[tid] = w[h*KW + tid];
    for (int i = tid; i < 160*16; i += 256) {
        int row = i >> 4, c4 = (i & 15) << 2;
        int n = n0 + row - 16;
        float4 val = make_float4(0.f, 0.f, 0.f, 0.f);
        if (n >= 0 && n < NS) {
            uint2 u = *reinterpret_cast<const uint2*>(vb + (size_t)n*DH + c4);
            __nv_bfloat162 p0 = *reinterpret_cast<__nv_bfloat162*>(&u.x);
            __nv_bfloat162 p1 = *reinterpret_cast<__nv_bfloat162*>(&u.y);
            val.x = __bfloat162float(p0.x); val.y = __bfloat162float(p0.y);
            val.z = __bfloat162float(p1.x); val.w = __bfloat162float(p1.y);
        }
        *reinterpret_cast<float4*>(&vs[row][c4]) = val;
    }
    __syncthreads();
    int d = tid & 63, g = tid >> 6;
#pragma unroll 4
    for (int j = 0; j < 32; j++) {
        int n = g*32 + j;
        float s = 0.f;
#pragma unroll
        for (int k = 0; k < KW; k++) s += ws[k] * vs[n + k][d];
        g_ohf[((size_t)b*NS + n0 + n)*NI + h*64 + d] = s;
    }
}

// ---------------- host launcher ------------------------------------------------
template <typename T>
static T* symp(T& sym) { void* p = nullptr; cudaGetSymbolAddress(&p, sym); return (T*)p; }

extern "C" void kernel_launch(void* const* d_in, const int* in_sizes, int n_in,
                              void* d_out, int out_size)
{
    const float* x     = (const float*)d_in[0];
    const float* ln_g  = (const float*)d_in[1];
    const float* ln_b  = (const float*)d_in[2];
    const float* w_qkv = (const float*)d_in[3];
    const float* w_out = (const float*)d_in[4];
    const float* b_out = (const float*)d_in[5];
    const float* w_res = (const float*)d_in[6];
    float* out = (float*)d_out;

    bf16* p_xnb = symp(*g_xnb);   bf16* p_wqkvT = symp(*g_wqkvT);
    bf16* p_woutT = symp(*g_woutT);
    bf16* p_qb  = symp(*g_qb);    bf16* p_kb  = symp(*g_kb);
    bf16* p_vT  = symp(*g_vT);
    bf16* p_qlb = symp(*g_qlb);   bf16* p_klb = symp(*g_klb);
    bf16* p_a1b = symp(*g_a1b);   bf16* p_a2b = symp(*g_a2b);
    bf16* p_a3b = symp(*g_a3b);
    bf16* p_zA  = symp(*g_zA);    bf16* p_zAT = symp(*g_zAT);
    bf16* p_zB  = symp(*g_zB);    bf16* p_zBT = symp(*g_zBT);
    bf16* p_xz  = symp(*g_xz);    bf16* p_xzT = symp(*g_xzT);
    bf16* p_t1T = symp(*g_t1T);   bf16* p_t2T = symp(*g_t2T);
    bf16* p_w3T = symp(*g_w3T);   bf16* p_uT  = symp(*g_uT);
    bf16* p_ohb = symp(*g_ohb);

    static bool attr_set = false;
    if (!attr_set) {
        cudaFuncSetAttribute(gemm_wmma<128>, cudaFuncAttributeMaxDynamicSharedMemorySize, DSMEM_128);
        cudaFuncSetAttribute(gemm_wmma<64>,  cudaFuncAttributeMaxDynamicSharedMemorySize, DSMEM_64);
        cudaFuncSetAttribute(gemm_pinv64, cudaFuncAttributeMaxDynamicSharedMemorySize, DSMEM_P64);
        cudaFuncSetAttribute(gemm_a3v, cudaFuncAttributeMaxDynamicSharedMemorySize, DSMEM_A3V);
        cudaFuncSetAttribute(attn_wmma, cudaFuncAttributeMaxDynamicSharedMemorySize, ATT_DSMEM);
        attr_set = true;
    }

    const long long SM2 = 65536, SW = (long long)DH*NM;

    ln_kernel<<<NB*NS, 128>>>(x, ln_g, ln_b);
    wqkvT_kernel<<<768*512/256, 256>>>(w_qkv);
    woutT_kernel<<<512*256/256, 256>>>(w_out);

    // QKV -> bf16 q/k/v (+vT)
    gemm_wmma<128><<<dim3(6, 256, 1), 256, DSMEM_128>>>(
        p_xnb, p_wqkvT, 512, 0, 0, 0, 0.f, 1.f, 1.f,
        nullptr, nullptr, nullptr, nullptr, nullptr, 0, 0);

    landmark_kernel<<<(NBH*NM*DH)/256, 256>>>(p_qb, p_qlb);
    landmark_kernel<<<(NBH*NM*DH)/256, 256>>>(p_kb, p_klb);

    // a1 = softmax(q @ kl^T), a2 = softmax(ql @ kl^T)
    attn_wmma<<<dim3(NS/64, NBH), 256, ATT_DSMEM>>>(p_qb,  p_a1b, NS);
    attn_wmma<<<dim3(NM/64, NBH), 256, ATT_DSMEM>>>(p_qlb, p_a2b, NM);

    // exp(ql @ k^T) -> bf16 a3b, row sums, split-K a3@v, reduce+normalize
    gemm_wmma<128><<<dim3(NS/128, 2, NBH), 256, DSMEM_128>>>(
        p_qlb, p_kb, 64, (long long)NM*DH, (long long)NS*DH, 5, 0.f, 1.f, 1.f,
        p_a3b, nullptr, nullptr, nullptr, nullptr, (long long)NM*NS, NS);
    rowsum_kernel<<<(NBH*NM)/8, 256>>>();
    gemm_a3v<<<dim3(SPL, 2, NBH), 256, DSMEM_A3V>>>();
    w3red_kernel<<<(NBH*NM*DH)/256, 256>>>();

    init_red_kernel<<<1, 1>>>();
    pinv_prep_kernel<<<32, 256>>>();
    zinit_kernel<<<(NBH*NM*NM)/256, 256>>>();

    bf16 *zc = p_zA, *zcT = p_zAT, *zn = p_zB, *znT = p_zBT;
    dim3 gp(2, 4, NBH);
    for (int it = 0; it < 6; it++) {
        gemm_pinv64<<<gp, 256, DSMEM_P64>>>(p_a2b, zcT, 0.f,  1.f,  1.f,   p_xz,    p_xzT);
        gemm_pinv64<<<gp, 256, DSMEM_P64>>>(p_xz, p_xzT, 7.f, -1.f,  1.f,   nullptr, p_t1T);
        gemm_pinv64<<<gp, 256, DSMEM_P64>>>(p_xz, p_t1T, 15.f, -1.f, 1.f,   nullptr, p_t2T);
        gemm_pinv64<<<gp, 256, DSMEM_P64>>>(zc,   p_t2T, 13.f, -1.f, 0.25f, zn,      znT);
        bf16* t;
        t = zc; zc = zn; zn = t;
        t = zcT; zcT = znT; znT = t;
    }
    // u^T = (z @ w3)^T
    gemm_wmma<64><<<dim3(1, 2, NBH), 256, DSMEM_64>>>(zc, p_w3T, 256, SM2, SW, 2, 0.f, 1.f, 1.f,
                                                      nullptr, p_uT, nullptr, nullptr, nullptr, 0, 0);
    // conv residual then oh = a1@u + conv
    conv_kernel<<<dim3(NS/128, NBH), 256>>>(w_res);
    gemm_wmma<64><<<dim3(1, 32, NBH), 256, DSMEM_64>>>(p_a1b, p_uT, 256, (long long)NS*NM, SW, 3,
                                                       0.f, 1.f, 1.f, nullptr, nullptr, nullptr,
                                                       nullptr, nullptr, 0, 0);
    // out = x + oh @ w_out + b
    gemm_wmma<128><<<dim3(4, 256, 1), 256, DSMEM_128>>>(p_ohb, p_woutT, 256, 0, 0, 4,
                                                        0.f, 1.f, 1.f, nullptr, nullptr, out,
                                                        b_out, x, 0, 0);
}

// round 16
// speedup vs baseline: 1.0642x; 1.0642x over previous
#include <cuda_runtime.h>
#include <cuda_bf16.h>
#include <mma.h>
#include <cstdint>

using namespace nvcuda;

constexpr int NB  = 8;
constexpr int NS  = 4096;
constexpr int ND  = 512;
constexpr int NH  = 4;
constexpr int DH  = 64;
constexpr int NI  = 256;
constexpr int NM  = 256;
constexpr int NBH = 32;
constexpr int KW  = 33;
constexpr int SPL = 4;

typedef __nv_bfloat16 bf16;

// ---------------- scratch ----------------------------------------------------
__device__ float g_ohf[(size_t)NB*NS*NI];
__device__ float g_s3 [(size_t)NBH*NM*NS];
__device__ float g_w3p[(size_t)SPL*NBH*NM*DH];
__device__ unsigned g_red[2];

__device__ bf16 g_xnb [(size_t)NB*NS*ND];
__device__ bf16 g_wqkvT[768*512];
__device__ bf16 g_woutT[512*256];
__device__ bf16 g_qb  [(size_t)NBH*NS*DH];
__device__ bf16 g_kb  [(size_t)NBH*NS*DH];
__device__ bf16 g_vb  [(size_t)NBH*NS*DH];
__device__ bf16 g_vT  [(size_t)NBH*DH*NS];
__device__ bf16 g_qlb [NBH*NM*DH];
__device__ bf16 g_klb [NBH*NM*DH];
__device__ bf16 g_a1b [(size_t)NBH*NS*NM];
__device__ bf16 g_a2b [NBH*NM*NM];
__device__ bf16 g_a3b [(size_t)NBH*NM*NS];
__device__ bf16 g_zA  [NBH*NM*NM];
__device__ bf16 g_zAT [NBH*NM*NM];
__device__ bf16 g_zB  [NBH*NM*NM];
__device__ bf16 g_zBT [NBH*NM*NM];
__device__ bf16 g_xz  [NBH*NM*NM];
__device__ bf16 g_xzT [NBH*NM*NM];
__device__ bf16 g_t1T [NBH*NM*NM];
__device__ bf16 g_t2T [NBH*NM*NM];
__device__ bf16 g_w3T [NBH*DH*NM];
__device__ bf16 g_uT  [NBH*DH*NM];
__device__ bf16 g_ohb [(size_t)NB*NS*NI];

__device__ __forceinline__ uint32_t pack_bf2(float a, float b) {
    __nv_bfloat162 h = __floats2bfloat162_rn(a, b);
    return *reinterpret_cast<uint32_t*>(&h);
}
__device__ __forceinline__ uint32_t smem_u32(const void* p) {
    uint32_t a;
    asm("{ .reg .u64 t; cvta.to.shared.u64 t, %1; cvt.u32.u64 %0, t; }" : "=r"(a) : "l"(p));
    return a;
}
__device__ __forceinline__ void cp16(void* dst, const void* src) {
    asm volatile("cp.async.cg.shared.global [%0], [%1], 16;"
                 :: "r"(smem_u32(dst)), "l"(src) : "memory");
}
__device__ __forceinline__ void cp_commit() { asm volatile("cp.async.commit_group;" ::: "memory"); }
__device__ __forceinline__ void cp_wait0()  { asm volatile("cp.async.wait_group 0;" ::: "memory"); }
__device__ __forceinline__ void cp_wait1()  { asm volatile("cp.async.wait_group 1;" ::: "memory"); }

// ============================================================================
// wmma bf16 GEMM: 256 thr / 8 warps, block 128xBN, warp 32x(BN/2), BK=32,
// cp.async 2-stage. D = A[M,K] @ BT[N,K]^T, fp32 accum, fused epilogues.
// ============================================================================
constexpr int LDT = 40;

template <int BN>
__global__ __launch_bounds__(256, 2) void gemm_wmma(
    const bf16* __restrict__ A, const bf16* __restrict__ BT,
    int K, long long sA, long long sB,
    int mode, float aCoef, float sCoef, float scl,
    bf16* outb, bf16* outbT, float* __restrict__ outf,
    const float* __restrict__ bias, const float* __restrict__ xres,
    long long sC, int rsC)
{
    constexpr int NJ   = BN / 32;
    constexpr int LDCS = BN + 4;

    extern __shared__ __align__(32) char smem[];
    bf16* As = reinterpret_cast<bf16*>(smem);
    bf16* Bs = As + 2*128*LDT;
    float* Cs = reinterpret_cast<float*>(smem);

    int tid = threadIdx.x, wid = tid >> 5;
    int bz = blockIdx.z;
    const bf16* Ab = A  + (size_t)bz * sA;
    const bf16* Bb = BT + (size_t)bz * sB;
    int n0 = blockIdx.x * BN, m0 = blockIdx.y * 128;
    int wm = (wid & 3) * 32, wn = (wid >> 2) * (NJ * 16);

    wmma::fragment<wmma::accumulator, 16, 16, 16, float> acc[2][NJ];
#pragma unroll
    for (int i = 0; i < 2; i++)
#pragma unroll
        for (int j = 0; j < NJ; j++) wmma::fill_fragment(acc[i][j], 0.0f);

    int arow = tid >> 2, akc = (tid & 3) << 3;
    int nch = K >> 5;

    auto load_chunk = [&](int st, int k0) {
        bf16* Ad = As + st * 128*LDT;
        bf16* Bd = Bs + st * BN*LDT;
#pragma unroll
        for (int i = 0; i < 2; i++)
            cp16(Ad + (arow + i*64)*LDT + akc,
                 Ab + (size_t)(m0 + arow + i*64)*K + k0 + akc);
#pragma unroll
        for (int i = 0; i < (BN == 128 ? 2 : 1); i++)
            cp16(Bd + (arow + i*64)*LDT + akc,
                 Bb + (size_t)(n0 + arow + i*64)*K + k0 + akc);
        cp_commit();
    };

    load_chunk(0, 0);
    for (int c = 0; c < nch; c++) {
        bool more = (c + 1 < nch);
        if (more) load_chunk((c + 1) & 1, (c + 1) << 5);
        if (more) cp_wait1(); else cp_wait0();
        __syncthreads();
        const bf16* Ar = As + (c & 1) * 128*LDT;
        const bf16* Br = Bs + (c & 1) * BN*LDT;
#pragma unroll
        for (int kk = 0; kk < 32; kk += 16) {
            wmma::fragment<wmma::matrix_a, 16, 16, 16, bf16, wmma::row_major> af[2];
            wmma::fragment<wmma::matrix_b, 16, 16, 16, bf16, wmma::col_major> bfr[NJ];
#pragma unroll
            for (int i = 0; i < 2; i++)
                wmma::load_matrix_sync(af[i], Ar + (wm + i*16)*LDT + kk, LDT);
#pragma unroll
            for (int j = 0; j < NJ; j++)
                wmma::load_matrix_sync(bfr[j], Br + (wn + j*16)*LDT + kk, LDT);
#pragma unroll
            for (int i = 0; i < 2; i++)
#pragma unroll
                for (int j = 0; j < NJ; j++)
                    wmma::mma_sync(acc[i][j], af[i], bfr[j], acc[i][j]);
        }
        __syncthreads();
    }
#pragma unroll
    for (int i = 0; i < 2; i++)
#pragma unroll
        for (int j = 0; j < NJ; j++)
            wmma::store_matrix_sync(Cs + (wm + i*16)*LDCS + wn + j*16, acc[i][j],
                                    LDCS, wmma::mem_row_major);
    __syncthreads();

    int row = tid >> 1, c0 = (tid & 1) * (BN/2);
    int r = m0 + row;
    const float* cp = Cs + row*LDCS + c0;

    if (mode == 0) {                       // QKV scatter -> bf16 q/k/v (+vT)
        int b = r >> 12, n = r & (NS - 1);
#pragma unroll 8
        for (int c = 0; c < BN/2; c++) {
            int col = n0 + c0 + c;
            int part = col >> 8, e = col & 255;
            int h = e >> 6, d = e & 63;
            float v = cp[c];
            size_t hb = (((size_t)b*NH + h)*NS + n)*DH + d;
            if (part == 0) g_qb[hb] = __float2bfloat16(v * 0.125f);
            else if (part == 1) g_kb[hb] = __float2bfloat16(v);
            else {
                bf16 hv = __float2bfloat16(v);
                g_vb[hb] = hv;
                g_vT[(((size_t)b*NH + h)*DH + d)*NS + n] = hv;
            }
        }
    } else if (mode == 1) {                // pinv: scl*(sCoef*acc + aCoef*A)
        size_t ob = (size_t)bz * 65536;
#pragma unroll 8
        for (int c = 0; c < BN/2; c++) {
            int col = n0 + c0 + c;
            float v = sCoef * cp[c];
            if (aCoef != 0.0f) v += aCoef * __bfloat162float(Ab[(size_t)r*K + col]);
            v *= scl;
            bf16 hv = __float2bfloat16(v);
            if (outb)  outb [ob + (size_t)r*256 + col] = hv;
            if (outbT) outbT[ob + (size_t)col*256 + r] = hv;
        }
    } else if (mode == 2) {                // transposed bf16 write (u^T / w3^T)
        size_t ob = (size_t)bz * (DH*NM);
#pragma unroll 8
        for (int c = 0; c < BN/2; c++)
            outbT[ob + (size_t)(n0 + c0 + c)*256 + r] = __float2bfloat16(cp[c]);
    } else if (mode == 3) {                // a1@u + conv residual -> bf16 oh
        int b = bz >> 2, h = bz & 3;
        size_t base = ((size_t)b*NS + r)*NI + h*64 + n0 + c0;
#pragma unroll 8
        for (int c = 0; c < BN/2; c++)
            g_ohb[base + c] = __float2bfloat16(cp[c] + g_ohf[base + c]);
    } else if (mode == 4) {                // proj: out = acc + bias + x
        size_t base = (size_t)r * ND;
#pragma unroll 8
        for (int c = 0; c < BN/2; c++) {
            int col = n0 + c0 + c;
            outf[base + col] = cp[c] + bias[col] + xres[base + col];
        }
    } else {                               // 5: raw fp32 scores
        float* op = outf + (size_t)bz*sC + (size_t)r*rsC + n0 + c0;
#pragma unroll 8
        for (int c = 0; c < BN/2; c++) op[c] = cp[c];
    }
}

constexpr int DSMEM_128 = 128 * (128 + 4) * 4;
constexpr int DSMEM_64  = 128 * (64 + 4) * 4;

// ============================================================================
// gemm_pinv64: BM=64, BN=128, K=256, BK=64 (4 serial chunks). pinv epilogue.
// ============================================================================
constexpr int LDT2 = 72;
constexpr int DSMEM_P64 = 2 * (64 + 128) * LDT2 * 2;   // 55296 (> C 33792)

__global__ __launch_bounds__(256, 2) void gemm_pinv64(
    const bf16* __restrict__ A, const bf16* __restrict__ BT,
    float aCoef, float sCoef, float scl,
    bf16* outb, bf16* outbT)
{
    constexpr int LDCS = 132;
    extern __shared__ __align__(32) char smem[];
    bf16* As = reinterpret_cast<bf16*>(smem);      // 2 x 64x72
    bf16* Bs = As + 2*64*LDT2;                     // 2 x 128x72
    float* Cs = reinterpret_cast<float*>(smem);    // 64x132

    int tid = threadIdx.x, wid = tid >> 5;
    int bz = blockIdx.z;
    const bf16* Ab = A  + (size_t)bz * 65536;
    const bf16* Bb = BT + (size_t)bz * 65536;
    int n0 = blockIdx.x * 128, m0 = blockIdx.y * 64;
    int wm = (wid & 1) * 32, wn = (wid >> 1) * 32;

    wmma::fragment<wmma::accumulator, 16, 16, 16, float> acc[2][2];
#pragma unroll
    for (int i = 0; i < 2; i++)
#pragma unroll
        for (int j = 0; j < 2; j++) wmma::fill_fragment(acc[i][j], 0.0f);

    int arow = tid >> 3, akc = (tid & 7) << 3;

    auto load_chunk = [&](int st, int k0) {
        bf16* Ad = As + st * 64*LDT2;
        bf16* Bd = Bs + st * 128*LDT2;
#pragma unroll
        for (int i = 0; i < 2; i++)
            cp16(Ad + (arow + i*32)*LDT2 + akc,
                 Ab + (size_t)(m0 + arow + i*32)*256 + k0 + akc);
#pragma unroll
        for (int i = 0; i < 4; i++)
            cp16(Bd + (arow + i*32)*LDT2 + akc,
                 Bb + (size_t)(n0 + arow + i*32)*256 + k0 + akc);
        cp_commit();
    };

    load_chunk(0, 0);
    for (int c = 0; c < 4; c++) {
        bool more = (c + 1 < 4);
        if (more) load_chunk((c + 1) & 1, (c + 1) << 6);
        if (more) cp_wait1(); else cp_wait0();
        __syncthreads();
        const bf16* Ar = As + (c & 1) * 64*LDT2;
        const bf16* Br = Bs + (c & 1) * 128*LDT2;
#pragma unroll
        for (int kk = 0; kk < 64; kk += 16) {
            wmma::fragment<wmma::matrix_a, 16, 16, 16, bf16, wmma::row_major> af[2];
            wmma::fragment<wmma::matrix_b, 16, 16, 16, bf16, wmma::col_major> bfr[2];
#pragma unroll
            for (int i = 0; i < 2; i++)
                wmma::load_matrix_sync(af[i], Ar + (wm + i*16)*LDT2 + kk, LDT2);
#pragma unroll
            for (int j = 0; j < 2; j++)
                wmma::load_matrix_sync(bfr[j], Br + (wn + j*16)*LDT2 + kk, LDT2);
#pragma unroll
            for (int i = 0; i < 2; i++)
#pragma unroll
                for (int j = 0; j < 2; j++)
                    wmma::mma_sync(acc[i][j], af[i], bfr[j], acc[i][j]);
        }
        __syncthreads();
    }
#pragma unroll
    for (int i = 0; i < 2; i++)
#pragma unroll
        for (int j = 0; j < 2; j++)
            wmma::store_matrix_sync(Cs + (wm + i*16)*LDCS + wn + j*16, acc[i][j],
                                    LDCS, wmma::mem_row_major);
    __syncthreads();

    int row = tid >> 2, c0 = (tid & 3) * 32;
    int r = m0 + row;
    const float* cp = Cs + row*LDCS + c0;
    size_t ob = (size_t)bz * 65536;
#pragma unroll 8
    for (int c = 0; c < 32; c++) {
        int col = n0 + c0 + c;
        float v = sCoef * cp[c];
        if (aCoef != 0.0f) v += aCoef * __bfloat162float(Ab[(size_t)r*256 + col]);
        v *= scl;
        bf16 hv = __float2bfloat16(v);
        if (outb)  outb [ob + (size_t)r*256 + col] = hv;
        if (outbT) outbT[ob + (size_t)col*256 + r] = hv;
    }
}

// ============================================================================
// gemm_a3v: split-K w3 partials = a3 @ v. Grid (SPL, 2, NBH).
// ============================================================================
__global__ __launch_bounds__(256, 2) void gemm_a3v()
{
    constexpr int LDCS = 68;
    extern __shared__ __align__(32) char smem[];
    bf16* As = reinterpret_cast<bf16*>(smem);
    bf16* Bs = As + 2*128*LDT;
    float* Cs = reinterpret_cast<float*>(smem);

    int tid = threadIdx.x, wid = tid >> 5;
    int bz = blockIdx.z;
    int split = blockIdx.x;
    int koff = split * (NS / SPL);
    int m0 = blockIdx.y * 128;
    const bf16* Ab = g_a3b + (size_t)bz * NM * NS;
    const bf16* Bb = g_vT  + (size_t)bz * DH * NS;
    int wm = (wid & 3) * 32, wn = (wid >> 2) * 32;

    wmma::fragment<wmma::accumulator, 16, 16, 16, float> acc[2][2];
#pragma unroll
    for (int i = 0; i < 2; i++)
#pragma unroll
        for (int j = 0; j < 2; j++) wmma::fill_fragment(acc[i][j], 0.0f);

    int arow = tid >> 2, akc = (tid & 3) << 3;

    auto load_chunk = [&](int st, int k0) {
        bf16* Ad = As + st * 128*LDT;
        bf16* Bd = Bs + st * 64*LDT;
#pragma unroll
        for (int i = 0; i < 2; i++)
            cp16(Ad + (arow + i*64)*LDT + akc,
                 Ab + (size_t)(m0 + arow + i*64)*NS + koff + k0 + akc);
        cp16(Bd + arow*LDT + akc,
             Bb + (size_t)arow*NS + koff + k0 + akc);
        cp_commit();
    };

    const int NCH = (NS / SPL) / 32;
    load_chunk(0, 0);
    for (int c = 0; c < NCH; c++) {
        bool more = (c + 1 < NCH);
        if (more) load_chunk((c + 1) & 1, (c + 1) << 5);
        if (more) cp_wait1(); else cp_wait0();
        __syncthreads();
        const bf16* Ar = As + (c & 1) * 128*LDT;
        const bf16* Br = Bs + (c & 1) * 64*LDT;
#pragma unroll
        for (int kk = 0; kk < 32; kk += 16) {
            wmma::fragment<wmma::matrix_a, 16, 16, 16, bf16, wmma::row_major> af[2];
            wmma::fragment<wmma::matrix_b, 16, 16, 16, bf16, wmma::col_major> bfr[2];
#pragma unroll
            for (int i = 0; i < 2; i++)
                wmma::load_matrix_sync(af[i], Ar + (wm + i*16)*LDT + kk, LDT);
#pragma unroll
            for (int j = 0; j < 2; j++)
                wmma::load_matrix_sync(bfr[j], Br + (wn + j*16)*LDT + kk, LDT);
#pragma unroll
            for (int i = 0; i < 2; i++)
#pragma unroll
                for (int j = 0; j < 2; j++)
                    wmma::mma_sync(acc[i][j], af[i], bfr[j], acc[i][j]);
        }
        __syncthreads();
    }
#pragma unroll
    for (int i = 0; i < 2; i++)
#pragma unroll
        for (int j = 0; j < 2; j++)
            wmma::store_matrix_sync(Cs + (wm + i*16)*LDCS + wn + j*16, acc[i][j],
                                    LDCS, wmma::mem_row_major);
    __syncthreads();

    int row = tid >> 1, c0 = (tid & 1) * 32;
    int r = m0 + row;
    const float* cp = Cs + row*LDCS + c0;
    float* op = g_w3p + (((size_t)split*NBH + bz)*NM + r)*DH + c0;
#pragma unroll 8
    for (int c = 0; c < 32; c++) op[c] = cp[c];
}

constexpr int DSMEM_A3V = 128 * 68 * 4;

// ---------------- split-K reduce: w3T = sum partials ---------------------------
__global__ void w3red_kernel()
{
    int idx = blockIdx.x * blockDim.x + threadIdx.x;
    int d = idx & 63, m = (idx >> 6) & 255, bh = idx >> 14;
    float s = 0.f;
#pragma unroll
    for (int sp = 0; sp < SPL; sp++)
        s += g_w3p[(((size_t)sp*NBH + bh)*NM + m)*DH + d];
    g_w3T[(size_t)bh*DH*NM + (size_t)d*NM + m] = __float2bfloat16(s);
}

// ============================================================================
// attn_wmma: O = softmax(Q @ KL^T) rows of 256, bf16 out. 64 q-rows/block.
// ============================================================================
constexpr int ALQ = 72;
constexpr int ALS = 260;
constexpr int ATT_DSMEM = 64*ALQ*2 + 256*ALQ*2 + 64*ALS*4;

__global__ __launch_bounds__(256) void attn_wmma(
    const bf16* __restrict__ Q, bf16* __restrict__ O, int Ma)
{
    extern __shared__ __align__(32) char sm[];
    bf16* Qs = reinterpret_cast<bf16*>(sm);
    bf16* Ks = Qs + 64*ALQ;
    float* Ss = reinterpret_cast<float*>(Ks + 256*ALQ);

    int bh = blockIdx.y, r0 = blockIdx.x * 64;
    const bf16* Qb = Q + ((size_t)bh*Ma + r0)*DH;
    const bf16* Kb = g_klb + (size_t)bh*NM*DH;
    int tid = threadIdx.x, wid = tid >> 5;

    for (int i = tid; i < 64*8; i += 256) {
        int row = i >> 3, c8 = (i & 7) * 8;
        *reinterpret_cast<uint4*>(Qs + row*ALQ + c8) =
            *reinterpret_cast<const uint4*>(Qb + (size_t)row*DH + c8);
    }
    for (int i = tid; i < 256*8; i += 256) {
        int row = i >> 3, c8 = (i & 7) * 8;
        *reinterpret_cast<uint4*>(Ks + row*ALQ + c8) =
            *reinterpret_cast<const uint4*>(Kb + (size_t)row*DH + c8);
    }
    __syncthreads();

    int wm = (wid & 3) * 16, wn = (wid >> 2) * 128;
    wmma::fragment<wmma::accumulator, 16, 16, 16, float> acc[8];
#pragma unroll
    for (int j = 0; j < 8; j++) wmma::fill_fragment(acc[j], 0.0f);
#pragma unroll
    for (int kk = 0; kk < 64; kk += 16) {
        wmma::fragment<wmma::matrix_a, 16, 16, 16, bf16, wmma::row_major> af;
        wmma::load_matrix_sync(af, Qs + wm*ALQ + kk, ALQ);
#pragma unroll
        for (int j = 0; j < 8; j++) {
            wmma::fragment<wmma::matrix_b, 16, 16, 16, bf16, wmma::col_major> bfr;
            wmma::load_matrix_sync(bfr, Ks + (wn + j*16)*ALQ + kk, ALQ);
            wmma::mma_sync(acc[j], af, bfr, acc[j]);
        }
    }
#pragma unroll
    for (int j = 0; j < 8; j++)
        wmma::store_matrix_sync(Ss + wm*ALS + wn + j*16, acc[j], ALS, wmma::mem_row_major);
    __syncthreads();

    int row = tid >> 2, q4 = tid & 3;
    float* sp = Ss + row*ALS + q4*64;
    float mx = -1e30f;
#pragma unroll 16
    for (int c = 0; c < 64; c++) mx = fmaxf(mx, sp[c]);
    mx = fmaxf(mx, __shfl_xor_sync(~0u, mx, 1));
    mx = fmaxf(mx, __shfl_xor_sync(~0u, mx, 2));
    float sum = 0.f;
#pragma unroll 16
    for (int c = 0; c < 64; c++) { float e = __expf(sp[c] - mx); sp[c] = e; sum += e; }
    sum += __shfl_xor_sync(~0u, sum, 1);
    sum += __shfl_xor_sync(~0u, sum, 2);
    float inv = 1.0f / sum;
    bf16* Ob = O + ((size_t)bh*Ma + r0 + row)*NM + q4*64;
#pragma unroll
    for (int c = 0; c < 64; c += 4) {
        uint2 o2 = { pack_bf2(sp[c]*inv, sp[c+1]*inv), pack_bf2(sp[c+2]*inv, sp[c+3]*inv) };
        *reinterpret_cast<uint2*>(Ob + c) = o2;
    }
}

// ---------------- softmax over 4096 (s3 -> a3 bf16) ---------------------------
__global__ __launch_bounds__(256) void softmax4096_kernel()
{
    int row = blockIdx.x, bh = blockIdx.y;
    const float* sp = g_s3 + ((size_t)bh*NM + row)*NS;
    bf16* op = g_a3b + ((size_t)bh*NM + row)*NS;
    int t = threadIdx.x, wid = t >> 5, lid = t & 31;
    float v[16];
    const float4* sp4 = reinterpret_cast<const float4*>(sp) + t*4;
#pragma unroll
    for (int i = 0; i < 4; i++) {
        float4 x = sp4[i];
        v[i*4] = x.x; v[i*4+1] = x.y; v[i*4+2] = x.z; v[i*4+3] = x.w;
    }
    __shared__ float red[8];
    float mx = v[0];
#pragma unroll
    for (int i = 1; i < 16; i++) mx = fmaxf(mx, v[i]);
#pragma unroll
    for (int o = 16; o > 0; o >>= 1) mx = fmaxf(mx, __shfl_xor_sync(~0u, mx, o));
    if (lid == 0) red[wid] = mx;
    __syncthreads();
    mx = red[0];
#pragma unroll
    for (int i = 1; i < 8; i++) mx = fmaxf(mx, red[i]);
    float sum = 0.f;
#pragma unroll
    for (int i = 0; i < 16; i++) { v[i] = __expf(v[i] - mx); sum += v[i]; }
#pragma unroll
    for (int o = 16; o > 0; o >>= 1) sum += __shfl_xor_sync(~0u, sum, o);
    __syncthreads();
    if (lid == 0) red[wid] = sum;
    __syncthreads();
    sum = red[0];
#pragma unroll
    for (int i = 1; i < 8; i++) sum += red[i];
    float inv = 1.0f / sum;
    uint4 o4;
    o4.x = pack_bf2(v[0]*inv,  v[1]*inv);  o4.y = pack_bf2(v[2]*inv,  v[3]*inv);
    o4.z = pack_bf2(v[4]*inv,  v[5]*inv);  o4.w = pack_bf2(v[6]*inv,  v[7]*inv);
    reinterpret_cast<uint4*>(op)[t*2] = o4;
    o4.x = pack_bf2(v[8]*inv,  v[9]*inv);  o4.y = pack_bf2(v[10]*inv, v[11]*inv);
    o4.z = pack_bf2(v[12]*inv, v[13]*inv); o4.w = pack_bf2(v[14]*inv, v[15]*inv);
    reinterpret_cast<uint4*>(op)[t*2+1] = o4;
}

// ---------------- LayerNorm -> bf16 -----------------------------------------
__global__ __launch_bounds__(128) void ln_kernel(
    const float* __restrict__ x, const float* __restrict__ g, const float* __restrict__ b)
{
    int row = blockIdx.x, t = threadIdx.x;
    float4 v4 = reinterpret_cast<const float4*>(x + (size_t)row*ND)[t];
    float s = v4.x + v4.y + v4.z + v4.w;
    __shared__ float r1[4], r2[4];
#pragma unroll
    for (int o = 16; o > 0; o >>= 1) s += __shfl_xor_sync(~0u, s, o);
    if ((t & 31) == 0) r1[t >> 5] = s;
    __syncthreads();
    float mu = (r1[0]+r1[1]+r1[2]+r1[3]) * (1.0f/ND);
    float dx = v4.x-mu, dy = v4.y-mu, dz = v4.z-mu, dw = v4.w-mu;
    float ss = dx*dx + dy*dy + dz*dz + dw*dw;
#pragma unroll
    for (int o = 16; o > 0; o >>= 1) ss += __shfl_xor_sync(~0u, ss, o);
    if ((t & 31) == 0) r2[t >> 5] = ss;
    __syncthreads();
    float inv = rsqrtf((r2[0]+r2[1]+r2[2]+r2[3]) * (1.0f/ND) + 1e-5f);
    float4 gv = reinterpret_cast<const float4*>(g)[t];
    float4 bv = reinterpret_cast<const float4*>(b)[t];
    uint2 o2;
    o2.x = pack_bf2(dx*inv*gv.x + bv.x, dy*inv*gv.y + bv.y);
    o2.y = pack_bf2(dz*inv*gv.z + bv.z, dw*inv*gv.w + bv.w);
    reinterpret_cast<uint2*>(g_xnb + (size_t)row*ND)[t] = o2;
}

// ---------------- weight transposes ------------------------------------------
__global__ void wqkvT_kernel(const float* __restrict__ w) {
    int idx = blockIdx.x * blockDim.x + threadIdx.x;
    int k = idx & 511, n = idx >> 9;
    g_wqkvT[idx] = __float2bfloat16(w[(size_t)k*768 + n]);
}
__global__ void woutT_kernel(const float* __restrict__ w) {
    int idx = blockIdx.x * blockDim.x + threadIdx.x;
    int k = idx & 255, n = idx >> 8;
    g_woutT[idx] = __float2bfloat16(w[(size_t)k*512 + n]);
}

// ---------------- landmarks (bf16 in/out, fp32 accum) -------------------------
__global__ void landmark_kernel(const bf16* __restrict__ src, bf16* __restrict__ dst)
{
    int idx = blockIdx.x * blockDim.x + threadIdx.x;
    int d = idx & 63, j = (idx >> 6) & (NM - 1), bh = idx >> 14;
    const bf16* p = src + ((size_t)bh*NS + (size_t)j*16)*DH + d;
    float s = 0.f;
#pragma unroll
    for (int i = 0; i < 16; i++) s += __bfloat162float(p[(size_t)i*DH]);
    dst[idx] = __float2bfloat16(s * (1.0f/16.0f));
}

// ---------------- pinv prep / init -------------------------------------------
__global__ void init_red_kernel() { g_red[0] = 0u; g_red[1] = 0u; }

__global__ void pinv_prep_kernel()
{
    int i = blockIdx.x * blockDim.x + threadIdx.x;
    int bh = i >> 8, r = i & 255;
    const bf16* A = g_a2b + (size_t)bh*NM*NM;
    float rs = 0.f, cs = 0.f;
    for (int j = 0; j < NM; j++) {
        rs += __bfloat162float(A[(size_t)r*NM + j]);
        cs += __bfloat162float(A[(size_t)j*NM + r]);
    }
    atomicMax(&g_red[0], __float_as_uint(rs));
    atomicMax(&g_red[1], __float_as_uint(cs));
}

__global__ void zinit_kernel()
{
    float inv = 1.0f / (__uint_as_float(g_red[0]) * __uint_as_float(g_red[1]));
    int idx = blockIdx.x * blockDim.x + threadIdx.x;
    int j = idx & 255, i = (idx >> 8) & 255, bh = idx >> 16;
    float a = __bfloat162float(g_a2b[idx]) * inv;
    bf16 h = __float2bfloat16(a);
    g_zAT[idx] = h;
    g_zA[((size_t)bh*NM + j)*NM + i] = h;
}

// ---------------- conv (bf16 v in, fp32 out) ----------------------------------
__global__ __launch_bounds__(256) void conv_kernel(const float* __restrict__ w)
{
    __shared__ float vs[160][64];
    __shared__ float ws[KW];
    int bh = blockIdx.y, n0 = blockIdx.x * 128;
    int b = bh >> 2, h = bh & 3;
    int tid = threadIdx.x;
    const bf16* vb = g_vb + (size_t)bh*NS*DH;
    if (tid < KW) ws[tid] = w[h*KW + tid];
    for (int i = tid; i < 160*16; i += 256) {
        int row = i >> 4, c4 = (i & 15) << 2;
        int n = n0 + row - 16;
        float4 val = make_float4(0.f, 0.f, 0.f, 0.f);
        if (n >= 0 && n < NS) {
            uint2 u = *reinterpret_cast<const uint2*>(vb + (size_t)n*DH + c4);
            __nv_bfloat162 p0 = *reinterpret_cast<__nv_bfloat162*>(&u.x);
            __nv_bfloat162 p1 = *reinterpret_cast<__nv_bfloat162*>(&u.y);
            val.x = __bfloat162float(p0.x); val.y = __bfloat162float(p0.y);
            val.z = __bfloat162float(p1.x); val.w = __bfloat162float(p1.y);
        }
        *reinterpret_cast<float4*>(&vs[row][c4]) = val;
    }
    __syncthreads();
    int d = tid & 63, g = tid >> 6;
#pragma unroll 4
    for (int j = 0; j < 32; j++) {
        int n = g*32 + j;
        float s = 0.f;
#pragma unroll
        for (int k = 0; k < KW; k++) s += ws[k] * vs[n + k][d];
        g_ohf[((size_t)b*NS + n0 + n)*NI + h*64 + d] = s;
    }
}

// ---------------- host launcher ------------------------------------------------
template <typename T>
static T* symp(T& sym) { void* p = nullptr; cudaGetSymbolAddress(&p, sym); return (T*)p; }

extern "C" void kernel_launch(void* const* d_in, const int* in_sizes, int n_in,
                              void* d_out, int out_size)
{
    const float* x     = (const float*)d_in[0];
    const float* ln_g  = (const float*)d_in[1];
    const float* ln_b  = (const float*)d_in[2];
    const float* w_qkv = (const float*)d_in[3];
    const float* w_out = (const float*)d_in[4];
    const float* b_out = (const float*)d_in[5];
    const float* w_res = (const float*)d_in[6];
    float* out = (float*)d_out;

    bf16* p_xnb = symp(*g_xnb);   bf16* p_wqkvT = symp(*g_wqkvT);
    bf16* p_woutT = symp(*g_woutT);
    bf16* p_qb  = symp(*g_qb);    bf16* p_kb  = symp(*g_kb);
    bf16* p_vT  = symp(*g_vT);
    bf16* p_qlb = symp(*g_qlb);   bf16* p_klb = symp(*g_klb);
    bf16* p_a1b = symp(*g_a1b);   bf16* p_a2b = symp(*g_a2b);
    bf16* p_a3b = symp(*g_a3b);
    bf16* p_zA  = symp(*g_zA);    bf16* p_zAT = symp(*g_zAT);
    bf16* p_zB  = symp(*g_zB);    bf16* p_zBT = symp(*g_zBT);
    bf16* p_xz  = symp(*g_xz);    bf16* p_xzT = symp(*g_xzT);
    bf16* p_t1T = symp(*g_t1T);   bf16* p_t2T = symp(*g_t2T);
    bf16* p_w3T = symp(*g_w3T);   bf16* p_uT  = symp(*g_uT);
    bf16* p_ohb = symp(*g_ohb);
    float* p_s3 = symp(*g_s3);

    static bool attr_set = false;
    if (!attr_set) {
        cudaFuncSetAttribute(gemm_wmma<128>, cudaFuncAttributeMaxDynamicSharedMemorySize, DSMEM_128);
        cudaFuncSetAttribute(gemm_wmma<64>,  cudaFuncAttributeMaxDynamicSharedMemorySize, DSMEM_64);
        cudaFuncSetAttribute(gemm_pinv64, cudaFuncAttributeMaxDynamicSharedMemorySize, DSMEM_P64);
        cudaFuncSetAttribute(gemm_a3v, cudaFuncAttributeMaxDynamicSharedMemorySize, DSMEM_A3V);
        cudaFuncSetAttribute(attn_wmma, cudaFuncAttributeMaxDynamicSharedMemorySize, ATT_DSMEM);
        attr_set = true;
    }

    const long long SM2 = 65536, SW = (long long)DH*NM;

    ln_kernel<<<NB*NS, 128>>>(x, ln_g, ln_b);
    wqkvT_kernel<<<768*512/256, 256>>>(w_qkv);
    woutT_kernel<<<512*256/256, 256>>>(w_out);

    // QKV -> bf16 q/k/v (+vT)
    gemm_wmma<128><<<dim3(6, 256, 1), 256, DSMEM_128>>>(
        p_xnb, p_wqkvT, 512, 0, 0, 0, 0.f, 1.f, 1.f,
        nullptr, nullptr, nullptr, nullptr, nullptr, 0, 0);

    landmark_kernel<<<(NBH*NM*DH)/256, 256>>>(p_qb, p_qlb);
    landmark_kernel<<<(NBH*NM*DH)/256, 256>>>(p_kb, p_klb);

    // a1 = softmax(q @ kl^T), a2 = softmax(ql @ kl^T)
    attn_wmma<<<dim3(NS/64, NBH), 256, ATT_DSMEM>>>(p_qb,  p_a1b, NS);
    attn_wmma<<<dim3(NM/64, NBH), 256, ATT_DSMEM>>>(p_qlb, p_a2b, NM);

    // s3 = ql @ k^T (fp32) ; softmax -> a3 ; split-K a3@v -> w3T
    gemm_wmma<128><<<dim3(NS/128, 2, NBH), 256, DSMEM_128>>>(
        p_qlb, p_kb, 64, (long long)NM*DH, (long long)NS*DH, 5, 0.f, 1.f, 1.f,
        nullptr, nullptr, p_s3, nullptr, nullptr, (long long)NM*NS, NS);
    softmax4096_kernel<<<dim3(NM, NBH), 256>>>();
    gemm_a3v<<<dim3(SPL, 2, NBH), 256, DSMEM_A3V>>>();
    w3red_kernel<<<(NBH*NM*DH)/256, 256>>>();

    init_red_kernel<<<1, 1>>>();
    pinv_prep_kernel<<<32, 256>>>();
    zinit_kernel<<<(NBH*NM*NM)/256, 256>>>();

    bf16 *zc = p_zA, *zcT = p_zAT, *zn = p_zB, *znT = p_zBT;
    dim3 gp(2, 4, NBH);
    for (int it = 0; it < 6; it++) {
        gemm_pinv64<<<gp, 256, DSMEM_P64>>>(p_a2b, zcT, 0.f,  1.f,  1.f,   p_xz,    p_xzT);
        gemm_pinv64<<<gp, 256, DSMEM_P64>>>(p_xz, p_xzT, 7.f, -1.f,  1.f,   nullptr, p_t1T);
        gemm_pinv64<<<gp, 256, DSMEM_P64>>>(p_xz, p_t1T, 15.f, -1.f, 1.f,   nullptr, p_t2T);
        gemm_pinv64<<<gp, 256, DSMEM_P64>>>(zc,   p_t2T, 13.f, -1.f, 0.25f, zn,      znT);
        bf16* t;
        t = zc; zc = zn; zn = t;
        t = zcT; zcT = znT; znT = t;
    }
    // u^T = (z @ w3)^T
    gemm_wmma<64><<<dim3(1, 2, NBH), 256, DSMEM_64>>>(zc, p_w3T, 256, SM2, SW, 2, 0.f, 1.f, 1.f,
                                                      nullptr, p_uT, nullptr, nullptr, nullptr, 0, 0);
    // conv residual then oh = a1@u + conv
    conv_kernel<<<dim3(NS/128, NBH), 256>>>(w_res);
    gemm_wmma<64><<<dim3(1, 32, NBH), 256, DSMEM_64>>>(p_a1b, p_uT, 256, (long long)NS*NM, SW, 3,
                                                       0.f, 1.f, 1.f, nullptr, nullptr, nullptr,
                                                       nullptr, nullptr, 0, 0);
    // out = x + oh @ w_out + b
    gemm_wmma<128><<<dim3(4, 256, 1), 256, DSMEM_128>>>(p_ohb, p_woutT, 256, 0, 0, 4,
                                                        0.f, 1.f, 1.f, nullptr, nullptr, out,
                                                        b_out, x, 0, 0);
}

// round 17
// speedup vs baseline: 1.0829x; 1.0175x over previous
#include <cuda_runtime.h>
#include <cuda_bf16.h>
#include <mma.h>
#include <cstdint>

using namespace nvcuda;

constexpr int NB  = 8;
constexpr int NS  = 4096;
constexpr int ND  = 512;
constexpr int NH  = 4;
constexpr int DH  = 64;
constexpr int NI  = 256;
constexpr int NM  = 256;
constexpr int NBH = 32;
constexpr int KW  = 33;
constexpr int SPL = 4;

typedef __nv_bfloat16 bf16;

// ---------------- scratch ----------------------------------------------------
__device__ float g_ohf[(size_t)NB*NS*NI];
__device__ float g_s3 [(size_t)NBH*NM*NS];
__device__ float g_w3p[(size_t)SPL*NBH*NM*DH];
__device__ unsigned g_red[2];

__device__ bf16 g_xnb [(size_t)NB*NS*ND];
__device__ bf16 g_wqkvT[768*512];
__device__ bf16 g_woutT[512*256];
__device__ bf16 g_qb  [(size_t)NBH*NS*DH];
__device__ bf16 g_kb  [(size_t)NBH*NS*DH];
__device__ bf16 g_vb  [(size_t)NBH*NS*DH];
__device__ bf16 g_vT  [(size_t)NBH*DH*NS];
__device__ bf16 g_qlb [NBH*NM*DH];
__device__ bf16 g_klb [NBH*NM*DH];
__device__ bf16 g_a1b [(size_t)NBH*NS*NM];
__device__ bf16 g_a2b [NBH*NM*NM];
__device__ bf16 g_a3b [(size_t)NBH*NM*NS];
__device__ bf16 g_zA  [NBH*NM*NM];
__device__ bf16 g_zAT [NBH*NM*NM];
__device__ bf16 g_zB  [NBH*NM*NM];
__device__ bf16 g_zBT [NBH*NM*NM];
__device__ bf16 g_xz  [NBH*NM*NM];
__device__ bf16 g_xzT [NBH*NM*NM];
__device__ bf16 g_t1T [NBH*NM*NM];
__device__ bf16 g_t2T [NBH*NM*NM];
__device__ bf16 g_w3T [NBH*DH*NM];
__device__ bf16 g_uT  [NBH*DH*NM];
__device__ bf16 g_ohb [(size_t)NB*NS*NI];

__device__ __forceinline__ uint32_t pack_bf2(float a, float b) {
    __nv_bfloat162 h = __floats2bfloat162_rn(a, b);
    return *reinterpret_cast<uint32_t*>(&h);
}
__device__ __forceinline__ uint32_t smem_u32(const void* p) {
    uint32_t a;
    asm("{ .reg .u64 t; cvta.to.shared.u64 t, %1; cvt.u32.u64 %0, t; }" : "=r"(a) : "l"(p));
    return a;
}
__device__ __forceinline__ void cp16(void* dst, const void* src) {
    asm volatile("cp.async.cg.shared.global [%0], [%1], 16;"
                 :: "r"(smem_u32(dst)), "l"(src) : "memory");
}
__device__ __forceinline__ void cp_commit() { asm volatile("cp.async.commit_group;" ::: "memory"); }
__device__ __forceinline__ void cp_wait0()  { asm volatile("cp.async.wait_group 0;" ::: "memory"); }
__device__ __forceinline__ void cp_wait1()  { asm volatile("cp.async.wait_group 1;" ::: "memory"); }

constexpr int LDT  = 40;   // BK=32 pitch (used by gemm_a3v)
constexpr int LDT2 = 72;   // BK=64 pitch

// ============================================================================
// wmma bf16 GEMM: 256 thr / 8 warps, block 128xBN, warp 32x(BN/2), BK=64,
// cp.async 2-stage. D = A[M,K] @ BT[N,K]^T, fp32 accum, fused epilogues.
// ============================================================================
template <int BN>
__global__ __launch_bounds__(256, 2) void gemm_wmma(
    const bf16* __restrict__ A, const bf16* __restrict__ BT,
    int K, long long sA, long long sB,
    int mode, float aCoef, float sCoef, float scl,
    bf16* outb, bf16* outbT, float* __restrict__ outf,
    const float* __restrict__ bias, const float* __restrict__ xres,
    long long sC, int rsC)
{
    constexpr int NJ   = BN / 32;
    constexpr int LDCS = BN + 4;

    extern __shared__ __align__(32) char smem[];
    bf16* As = reinterpret_cast<bf16*>(smem);          // 2 x 128 x LDT2
    bf16* Bs = As + 2*128*LDT2;                        // 2 x BN x LDT2
    float* Cs = reinterpret_cast<float*>(smem);

    int tid = threadIdx.x, wid = tid >> 5;
    int bz = blockIdx.z;
    const bf16* Ab = A  + (size_t)bz * sA;
    const bf16* Bb = BT + (size_t)bz * sB;
    int n0 = blockIdx.x * BN, m0 = blockIdx.y * 128;
    int wm = (wid & 3) * 32, wn = (wid >> 2) * (NJ * 16);

    wmma::fragment<wmma::accumulator, 16, 16, 16, float> acc[2][NJ];
#pragma unroll
    for (int i = 0; i < 2; i++)
#pragma unroll
        for (int j = 0; j < NJ; j++) wmma::fill_fragment(acc[i][j], 0.0f);

    int arow = tid >> 3, akc = (tid & 7) << 3;   // 32 rows x 64 cols per pass
    int nch = K >> 6;

    auto load_chunk = [&](int st, int k0) {
        bf16* Ad = As + st * 128*LDT2;
        bf16* Bd = Bs + st * BN*LDT2;
#pragma unroll
        for (int i = 0; i < 4; i++)
            cp16(Ad + (arow + i*32)*LDT2 + akc,
                 Ab + (size_t)(m0 + arow + i*32)*K + k0 + akc);
#pragma unroll
        for (int i = 0; i < BN/32; i++)
            cp16(Bd + (arow + i*32)*LDT2 + akc,
                 Bb + (size_t)(n0 + arow + i*32)*K + k0 + akc);
        cp_commit();
    };

    load_chunk(0, 0);
    for (int c = 0; c < nch; c++) {
        bool more = (c + 1 < nch);
        if (more) load_chunk((c + 1) & 1, (c + 1) << 6);
        if (more) cp_wait1(); else cp_wait0();
        __syncthreads();
        const bf16* Ar = As + (c & 1) * 128*LDT2;
        const bf16* Br = Bs + (c & 1) * BN*LDT2;
#pragma unroll
        for (int kk = 0; kk < 64; kk += 16) {
            wmma::fragment<wmma::matrix_a, 16, 16, 16, bf16, wmma::row_major> af[2];
            wmma::fragment<wmma::matrix_b, 16, 16, 16, bf16, wmma::col_major> bfr[NJ];
#pragma unroll
            for (int i = 0; i < 2; i++)
                wmma::load_matrix_sync(af[i], Ar + (wm + i*16)*LDT2 + kk, LDT2);
#pragma unroll
            for (int j = 0; j < NJ; j++)
                wmma::load_matrix_sync(bfr[j], Br + (wn + j*16)*LDT2 + kk, LDT2);
#pragma unroll
            for (int i = 0; i < 2; i++)
#pragma unroll
                for (int j = 0; j < NJ; j++)
                    wmma::mma_sync(acc[i][j], af[i], bfr[j], acc[i][j]);
        }
        __syncthreads();
    }
#pragma unroll
    for (int i = 0; i < 2; i++)
#pragma unroll
        for (int j = 0; j < NJ; j++)
            wmma::store_matrix_sync(Cs + (wm + i*16)*LDCS + wn + j*16, acc[i][j],
                                    LDCS, wmma::mem_row_major);
    __syncthreads();

    int row = tid >> 1, c0 = (tid & 1) * (BN/2);
    int r = m0 + row;
    const float* cp = Cs + row*LDCS + c0;

    if (mode == 0) {                       // QKV scatter -> bf16 q/k/v (+vT)
        int b = r >> 12, n = r & (NS - 1);
#pragma unroll 8
        for (int c = 0; c < BN/2; c++) {
            int col = n0 + c0 + c;
            int part = col >> 8, e = col & 255;
            int h = e >> 6, d = e & 63;
            float v = cp[c];
            size_t hb = (((size_t)b*NH + h)*NS + n)*DH + d;
            if (part == 0) g_qb[hb] = __float2bfloat16(v * 0.125f);
            else if (part == 1) g_kb[hb] = __float2bfloat16(v);
            else {
                bf16 hv = __float2bfloat16(v);
                g_vb[hb] = hv;
                g_vT[(((size_t)b*NH + h)*DH + d)*NS + n] = hv;
            }
        }
    } else if (mode == 1) {                // pinv: scl*(sCoef*acc + aCoef*A)
        size_t ob = (size_t)bz * 65536;
#pragma unroll 8
        for (int c = 0; c < BN/2; c++) {
            int col = n0 + c0 + c;
            float v = sCoef * cp[c];
            if (aCoef != 0.0f) v += aCoef * __bfloat162float(Ab[(size_t)r*K + col]);
            v *= scl;
            bf16 hv = __float2bfloat16(v);
            if (outb)  outb [ob + (size_t)r*256 + col] = hv;
            if (outbT) outbT[ob + (size_t)col*256 + r] = hv;
        }
    } else if (mode == 2) {                // transposed bf16 write (u^T / w3^T)
        size_t ob = (size_t)bz * (DH*NM);
#pragma unroll 8
        for (int c = 0; c < BN/2; c++)
            outbT[ob + (size_t)(n0 + c0 + c)*256 + r] = __float2bfloat16(cp[c]);
    } else if (mode == 3) {                // a1@u + conv residual -> bf16 oh
        int b = bz >> 2, h = bz & 3;
        size_t base = ((size_t)b*NS + r)*NI + h*64 + n0 + c0;
#pragma unroll 8
        for (int c = 0; c < BN/2; c++)
            g_ohb[base + c] = __float2bfloat16(cp[c] + g_ohf[base + c]);
    } else if (mode == 4) {                // proj: out = acc + bias + x
        size_t base = (size_t)r * ND;
#pragma unroll 8
        for (int c = 0; c < BN/2; c++) {
            int col = n0 + c0 + c;
            outf[base + col] = cp[c] + bias[col] + xres[base + col];
        }
    } else {                               // 5: raw fp32 scores
        float* op = outf + (size_t)bz*sC + (size_t)r*rsC + n0 + c0;
#pragma unroll 8
        for (int c = 0; c < BN/2; c++) op[c] = cp[c];
    }
}

constexpr int DSMEM_128 = 2 * (128 + 128) * LDT2 * 2;  // 73728 (> C 67584)
constexpr int DSMEM_64  = 2 * (128 + 64) * LDT2 * 2;   // 55296 (> C 34816)

// ============================================================================
// gemm_pinv64: BM=64, BN=128, K=256, BK=64 (4 serial chunks). pinv epilogue.
// ============================================================================
constexpr int DSMEM_P64 = 2 * (64 + 128) * LDT2 * 2;   // 55296

__global__ __launch_bounds__(256, 2) void gemm_pinv64(
    const bf16* __restrict__ A, const bf16* __restrict__ BT,
    float aCoef, float sCoef, float scl,
    bf16* outb, bf16* outbT)
{
    constexpr int LDCS = 132;
    extern __shared__ __align__(32) char smem[];
    bf16* As = reinterpret_cast<bf16*>(smem);
    bf16* Bs = As + 2*64*LDT2;
    float* Cs = reinterpret_cast<float*>(smem);

    int tid = threadIdx.x, wid = tid >> 5;
    int bz = blockIdx.z;
    const bf16* Ab = A  + (size_t)bz * 65536;
    const bf16* Bb = BT + (size_t)bz * 65536;
    int n0 = blockIdx.x * 128, m0 = blockIdx.y * 64;
    int wm = (wid & 1) * 32, wn = (wid >> 1) * 32;

    wmma::fragment<wmma::accumulator, 16, 16, 16, float> acc[2][2];
#pragma unroll
    for (int i = 0; i < 2; i++)
#pragma unroll
        for (int j = 0; j < 2; j++) wmma::fill_fragment(acc[i][j], 0.0f);

    int arow = tid >> 3, akc = (tid & 7) << 3;

    auto load_chunk = [&](int st, int k0) {
        bf16* Ad = As + st * 64*LDT2;
        bf16* Bd = Bs + st * 128*LDT2;
#pragma unroll
        for (int i = 0; i < 2; i++)
            cp16(Ad + (arow + i*32)*LDT2 + akc,
                 Ab + (size_t)(m0 + arow + i*32)*256 + k0 + akc);
#pragma unroll
        for (int i = 0; i < 4; i++)
            cp16(Bd + (arow + i*32)*LDT2 + akc,
                 Bb + (size_t)(n0 + arow + i*32)*256 + k0 + akc);
        cp_commit();
    };

    load_chunk(0, 0);
    for (int c = 0; c < 4; c++) {
        bool more = (c + 1 < 4);
        if (more) load_chunk((c + 1) & 1, (c + 1) << 6);
        if (more) cp_wait1(); else cp_wait0();
        __syncthreads();
        const bf16* Ar = As + (c & 1) * 64*LDT2;
        const bf16* Br = Bs + (c & 1) * 128*LDT2;
#pragma unroll
        for (int kk = 0; kk < 64; kk += 16) {
            wmma::fragment<wmma::matrix_a, 16, 16, 16, bf16, wmma::row_major> af[2];
            wmma::fragment<wmma::matrix_b, 16, 16, 16, bf16, wmma::col_major> bfr[2];
#pragma unroll
            for (int i = 0; i < 2; i++)
                wmma::load_matrix_sync(af[i], Ar + (wm + i*16)*LDT2 + kk, LDT2);
#pragma unroll
            for (int j = 0; j < 2; j++)
                wmma::load_matrix_sync(bfr[j], Br + (wn + j*16)*LDT2 + kk, LDT2);
#pragma unroll
            for (int i = 0; i < 2; i++)
#pragma unroll
                for (int j = 0; j < 2; j++)
                    wmma::mma_sync(acc[i][j], af[i], bfr[j], acc[i][j]);
        }
        __syncthreads();
    }
#pragma unroll
    for (int i = 0; i < 2; i++)
#pragma unroll
        for (int j = 0; j < 2; j++)
            wmma::store_matrix_sync(Cs + (wm + i*16)*LDCS + wn + j*16, acc[i][j],
                                    LDCS, wmma::mem_row_major);
    __syncthreads();

    int row = tid >> 2, c0 = (tid & 3) * 32;
    int r = m0 + row;
    const float* cp = Cs + row*LDCS + c0;
    size_t ob = (size_t)bz * 65536;
#pragma unroll 8
    for (int c = 0; c < 32; c++) {
        int col = n0 + c0 + c;
        float v = sCoef * cp[c];
        if (aCoef != 0.0f) v += aCoef * __bfloat162float(Ab[(size_t)r*256 + col]);
        v *= scl;
        bf16 hv = __float2bfloat16(v);
        if (outb)  outb [ob + (size_t)r*256 + col] = hv;
        if (outbT) outbT[ob + (size_t)col*256 + r] = hv;
    }
}

// ============================================================================
// gemm_a3v: split-K w3 partials = a3 @ v. Grid (SPL, 2, NBH). BK=32.
// ============================================================================
__global__ __launch_bounds__(256, 2) void gemm_a3v()
{
    constexpr int LDCS = 68;
    extern __shared__ __align__(32) char smem[];
    bf16* As = reinterpret_cast<bf16*>(smem);
    bf16* Bs = As + 2*128*LDT;
    float* Cs = reinterpret_cast<float*>(smem);

    int tid = threadIdx.x, wid = tid >> 5;
    int bz = blockIdx.z;
    int split = blockIdx.x;
    int koff = split * (NS / SPL);
    int m0 = blockIdx.y * 128;
    const bf16* Ab = g_a3b + (size_t)bz * NM * NS;
    const bf16* Bb = g_vT  + (size_t)bz * DH * NS;
    int wm = (wid & 3) * 32, wn = (wid >> 2) * 32;

    wmma::fragment<wmma::accumulator, 16, 16, 16, float> acc[2][2];
#pragma unroll
    for (int i = 0; i < 2; i++)
#pragma unroll
        for (int j = 0; j < 2; j++) wmma::fill_fragment(acc[i][j], 0.0f);

    int arow = tid >> 2, akc = (tid & 3) << 3;

    auto load_chunk = [&](int st, int k0) {
        bf16* Ad = As + st * 128*LDT;
        bf16* Bd = Bs + st * 64*LDT;
#pragma unroll
        for (int i = 0; i < 2; i++)
            cp16(Ad + (arow + i*64)*LDT + akc,
                 Ab + (size_t)(m0 + arow + i*64)*NS + koff + k0 + akc);
        cp16(Bd + arow*LDT + akc,
             Bb + (size_t)arow*NS + koff + k0 + akc);
        cp_commit();
    };

    const int NCH = (NS / SPL) / 32;
    load_chunk(0, 0);
    for (int c = 0; c < NCH; c++) {
        bool more = (c + 1 < NCH);
        if (more) load_chunk((c + 1) & 1, (c + 1) << 5);
        if (more) cp_wait1(); else cp_wait0();
        __syncthreads();
        const bf16* Ar = As + (c & 1) * 128*LDT;
        const bf16* Br = Bs + (c & 1) * 64*LDT;
#pragma unroll
        for (int kk = 0; kk < 32; kk += 16) {
            wmma::fragment<wmma::matrix_a, 16, 16, 16, bf16, wmma::row_major> af[2];
            wmma::fragment<wmma::matrix_b, 16, 16, 16, bf16, wmma::col_major> bfr[2];
#pragma unroll
            for (int i = 0; i < 2; i++)
                wmma::load_matrix_sync(af[i], Ar + (wm + i*16)*LDT + kk, LDT);
#pragma unroll
            for (int j = 0; j < 2; j++)
                wmma::load_matrix_sync(bfr[j], Br + (wn + j*16)*LDT + kk, LDT);
#pragma unroll
            for (int i = 0; i < 2; i++)
#pragma unroll
                for (int j = 0; j < 2; j++)
                    wmma::mma_sync(acc[i][j], af[i], bfr[j], acc[i][j]);
        }
        __syncthreads();
    }
#pragma unroll
    for (int i = 0; i < 2; i++)
#pragma unroll
        for (int j = 0; j < 2; j++)
            wmma::store_matrix_sync(Cs + (wm + i*16)*LDCS + wn + j*16, acc[i][j],
                                    LDCS, wmma::mem_row_major);
    __syncthreads();

    int row = tid >> 1, c0 = (tid & 1) * 32;
    int r = m0 + row;
    const float* cp = Cs + row*LDCS + c0;
    float* op = g_w3p + (((size_t)split*NBH + bz)*NM + r)*DH + c0;
#pragma unroll 8
    for (int c = 0; c < 32; c++) op[c] = cp[c];
}

constexpr int DSMEM_A3V = 128 * 68 * 4;

// ---------------- split-K reduce: w3T = sum partials ---------------------------
__global__ void w3red_kernel()
{
    int idx = blockIdx.x * blockDim.x + threadIdx.x;
    int d = idx & 63, m = (idx >> 6) & 255, bh = idx >> 14;
    float s = 0.f;
#pragma unroll
    for (int sp = 0; sp < SPL; sp++)
        s += g_w3p[(((size_t)sp*NBH + bh)*NM + m)*DH + d];
    g_w3T[(size_t)bh*DH*NM + (size_t)d*NM + m] = __float2bfloat16(s);
}

// ============================================================================
// attn_wmma: O = softmax(Q @ KL^T) rows of 256, bf16 out. 64 q-rows/block.
// ============================================================================
constexpr int ALQ = 72;
constexpr int ALS = 260;
constexpr int ATT_DSMEM = 64*ALQ*2 + 256*ALQ*2 + 64*ALS*4;

__global__ __launch_bounds__(256) void attn_wmma(
    const bf16* __restrict__ Q, bf16* __restrict__ O, int Ma)
{
    extern __shared__ __align__(32) char sm[];
    bf16* Qs = reinterpret_cast<bf16*>(sm);
    bf16* Ks = Qs + 64*ALQ;
    float* Ss = reinterpret_cast<float*>(Ks + 256*ALQ);

    int bh = blockIdx.y, r0 = blockIdx.x * 64;
    const bf16* Qb = Q + ((size_t)bh*Ma + r0)*DH;
    const bf16* Kb = g_klb + (size_t)bh*NM*DH;
    int tid = threadIdx.x, wid = tid >> 5;

    for (int i = tid; i < 64*8; i += 256) {
        int row = i >> 3, c8 = (i & 7) * 8;
        *reinterpret_cast<uint4*>(Qs + row*ALQ + c8) =
            *reinterpret_cast<const uint4*>(Qb + (size_t)row*DH + c8);
    }
    for (int i = tid; i < 256*8; i += 256) {
        int row = i >> 3, c8 = (i & 7) * 8;
        *reinterpret_cast<uint4*>(Ks + row*ALQ + c8) =
            *reinterpret_cast<const uint4*>(Kb + (size_t)row*DH + c8);
    }
    __syncthreads();

    int wm = (wid & 3) * 16, wn = (wid >> 2) * 128;
    wmma::fragment<wmma::accumulator, 16, 16, 16, float> acc[8];
#pragma unroll
    for (int j = 0; j < 8; j++) wmma::fill_fragment(acc[j], 0.0f);
#pragma unroll
    for (int kk = 0; kk < 64; kk += 16) {
        wmma::fragment<wmma::matrix_a, 16, 16, 16, bf16, wmma::row_major> af;
        wmma::load_matrix_sync(af, Qs + wm*ALQ + kk, ALQ);
#pragma unroll
        for (int j = 0; j < 8; j++) {
            wmma::fragment<wmma::matrix_b, 16, 16, 16, bf16, wmma::col_major> bfr;
            wmma::load_matrix_sync(bfr, Ks + (wn + j*16)*ALQ + kk, ALQ);
            wmma::mma_sync(acc[j], af, bfr, acc[j]);
        }
    }
#pragma unroll
    for (int j = 0; j < 8; j++)
        wmma::store_matrix_sync(Ss + wm*ALS + wn + j*16, acc[j], ALS, wmma::mem_row_major);
    __syncthreads();

    int row = tid >> 2, q4 = tid & 3;
    float* sp = Ss + row*ALS + q4*64;
    float mx = -1e30f;
#pragma unroll 16
    for (int c = 0; c < 64; c++) mx = fmaxf(mx, sp[c]);
    mx = fmaxf(mx, __shfl_xor_sync(~0u, mx, 1));
    mx = fmaxf(mx, __shfl_xor_sync(~0u, mx, 2));
    float sum = 0.f;
#pragma unroll 16
    for (int c = 0; c < 64; c++) { float e = __expf(sp[c] - mx); sp[c] = e; sum += e; }
    sum += __shfl_xor_sync(~0u, sum, 1);
    sum += __shfl_xor_sync(~0u, sum, 2);
    float inv = 1.0f / sum;
    bf16* Ob = O + ((size_t)bh*Ma + r0 + row)*NM + q4*64;
#pragma unroll
    for (int c = 0; c < 64; c += 4) {
        uint2 o2 = { pack_bf2(sp[c]*inv, sp[c+1]*inv), pack_bf2(sp[c+2]*inv, sp[c+3]*inv) };
        *reinterpret_cast<uint2*>(Ob + c) = o2;
    }
}

// ---------------- softmax over 4096 (s3 -> a3 bf16) ---------------------------
__global__ __launch_bounds__(256) void softmax4096_kernel()
{
    int row = blockIdx.x, bh = blockIdx.y;
    const float* sp = g_s3 + ((size_t)bh*NM + row)*NS;
    bf16* op = g_a3b + ((size_t)bh*NM + row)*NS;
    int t = threadIdx.x, wid = t >> 5, lid = t & 31;
    float v[16];
    const float4* sp4 = reinterpret_cast<const float4*>(sp) + t*4;
#pragma unroll
    for (int i = 0; i < 4; i++) {
        float4 x = sp4[i];
        v[i*4] = x.x; v[i*4+1] = x.y; v[i*4+2] = x.z; v[i*4+3] = x.w;
    }
    __shared__ float red[8];
    float mx = v[0];
#pragma unroll
    for (int i = 1; i < 16; i++) mx = fmaxf(mx, v[i]);
#pragma unroll
    for (int o = 16; o > 0; o >>= 1) mx = fmaxf(mx, __shfl_xor_sync(~0u, mx, o));
    if (lid == 0) red[wid] = mx;
    __syncthreads();
    mx = red[0];
#pragma unroll
    for (int i = 1; i < 8; i++) mx = fmaxf(mx, red[i]);
    float sum = 0.f;
#pragma unroll
    for (int i = 0; i < 16; i++) { v[i] = __expf(v[i] - mx); sum += v[i]; }
#pragma unroll
    for (int o = 16; o > 0; o >>= 1) sum += __shfl_xor_sync(~0u, sum, o);
    __syncthreads();
    if (lid == 0) red[wid] = sum;
    __syncthreads();
    sum = red[0];
#pragma unroll
    for (int i = 1; i < 8; i++) sum += red[i];
    float inv = 1.0f / sum;
    uint4 o4;
    o4.x = pack_bf2(v[0]*inv,  v[1]*inv);  o4.y = pack_bf2(v[2]*inv,  v[3]*inv);
    o4.z = pack_bf2(v[4]*inv,  v[5]*inv);  o4.w = pack_bf2(v[6]*inv,  v[7]*inv);
    reinterpret_cast<uint4*>(op)[t*2] = o4;
    o4.x = pack_bf2(v[8]*inv,  v[9]*inv);  o4.y = pack_bf2(v[10]*inv, v[11]*inv);
    o4.z = pack_bf2(v[12]*inv, v[13]*inv); o4.w = pack_bf2(v[14]*inv, v[15]*inv);
    reinterpret_cast<uint4*>(op)[t*2+1] = o4;
}

// ---------------- LayerNorm -> bf16 -----------------------------------------
__global__ __launch_bounds__(128) void ln_kernel(
    const float* __restrict__ x, const float* __restrict__ g, const float* __restrict__ b)
{
    int row = blockIdx.x, t = threadIdx.x;
    float4 v4 = reinterpret_cast<const float4*>(x + (size_t)row*ND)[t];
    float s = v4.x + v4.y + v4.z + v4.w;
    __shared__ float r1[4], r2[4];
#pragma unroll
    for (int o = 16; o > 0; o >>= 1) s += __shfl_xor_sync(~0u, s, o);
    if ((t & 31) == 0) r1[t >> 5] = s;
    __syncthreads();
    float mu = (r1[0]+r1[1]+r1[2]+r1[3]) * (1.0f/ND);
    float dx = v4.x-mu, dy = v4.y-mu, dz = v4.z-mu, dw = v4.w-mu;
    float ss = dx*dx + dy*dy + dz*dz + dw*dw;
#pragma unroll
    for (int o = 16; o > 0; o >>= 1) ss += __shfl_xor_sync(~0u, ss, o);
    if ((t & 31) == 0) r2[t >> 5] = ss;
    __syncthreads();
    float inv = rsqrtf((r2[0]+r2[1]+r2[2]+r2[3]) * (1.0f/ND) + 1e-5f);
    float4 gv = reinterpret_cast<const float4*>(g)[t];
    float4 bv = reinterpret_cast<const float4*>(b)[t];
    uint2 o2;
    o2.x = pack_bf2(dx*inv*gv.x + bv.x, dy*inv*gv.y + bv.y);
    o2.y = pack_bf2(dz*inv*gv.z + bv.z, dw*inv*gv.w + bv.w);
    reinterpret_cast<uint2*>(g_xnb + (size_t)row*ND)[t] = o2;
}

// ---------------- weight transposes ------------------------------------------
__global__ void wqkvT_kernel(const float* __restrict__ w) {
    int idx = blockIdx.x * blockDim.x + threadIdx.x;
    int k = idx & 511, n = idx >> 9;
    g_wqkvT[idx] = __float2bfloat16(w[(size_t)k*768 + n]);
}
__global__ void woutT_kernel(const float* __restrict__ w) {
    int idx = blockIdx.x * blockDim.x + threadIdx.x;
    int k = idx & 255, n = idx >> 8;
    g_woutT[idx] = __float2bfloat16(w[(size_t)k*512 + n]);
}

// ---------------- landmarks (bf16 in/out, fp32 accum) -------------------------
__global__ void landmark_kernel(const bf16* __restrict__ src, bf16* __restrict__ dst)
{
    int idx = blockIdx.x * blockDim.x + threadIdx.x;
    int d = idx & 63, j = (idx >> 6) & (NM - 1), bh = idx >> 14;
    const bf16* p = src + ((size_t)bh*NS + (size_t)j*16)*DH + d;
    float s = 0.f;
#pragma unroll
    for (int i = 0; i < 16; i++) s += __bfloat162float(p[(size_t)i*DH]);
    dst[idx] = __float2bfloat16(s * (1.0f/16.0f));
}

// ---------------- pinv prep / init -------------------------------------------
__global__ void init_red_kernel() { g_red[0] = 0u; g_red[1] = 0u; }

__global__ void pinv_prep_kernel()
{
    int i = blockIdx.x * blockDim.x + threadIdx.x;
    int bh = i >> 8, r = i & 255;
    const bf16* A = g_a2b + (size_t)bh*NM*NM;
    float rs = 0.f, cs = 0.f;
    for (int j = 0; j < NM; j++) {
        rs += __bfloat162float(A[(size_t)r*NM + j]);
        cs += __bfloat162float(A[(size_t)j*NM + r]);
    }
    atomicMax(&g_red[0], __float_as_uint(rs));
    atomicMax(&g_red[1], __float_as_uint(cs));
}

__global__ void zinit_kernel()
{
    float inv = 1.0f / (__uint_as_float(g_red[0]) * __uint_as_float(g_red[1]));
    int idx = blockIdx.x * blockDim.x + threadIdx.x;
    int j = idx & 255, i = (idx >> 8) & 255, bh = idx >> 16;
    float a = __bfloat162float(g_a2b[idx]) * inv;
    bf16 h = __float2bfloat16(a);
    g_zAT[idx] = h;
    g_zA[((size_t)bh*NM + j)*NM + i] = h;
}

// ---------------- conv (bf16 v in, fp32 out) ----------------------------------
__global__ __launch_bounds__(256) void conv_kernel(const float* __restrict__ w)
{
    __shared__ float vs[160][64];
    __shared__ float ws[KW];
    int bh = blockIdx.y, n0 = blockIdx.x * 128;
    int b = bh >> 2, h = bh & 3;
    int tid = threadIdx.x;
    const bf16* vb = g_vb + (size_t)bh*NS*DH;
    if (tid < KW) ws[tid] = w[h*KW + tid];
    for (int i = tid; i < 160*16; i += 256) {
        int row = i >> 4, c4 = (i & 15) << 2;
        int n = n0 + row - 16;
        float4 val = make_float4(0.f, 0.f, 0.f, 0.f);
        if (n >= 0 && n < NS) {
            uint2 u = *reinterpret_cast<const uint2*>(vb + (size_t)n*DH + c4);
            __nv_bfloat162 p0 = *reinterpret_cast<__nv_bfloat162*>(&u.x);
            __nv_bfloat162 p1 = *reinterpret_cast<__nv_bfloat162*>(&u.y);
            val.x = __bfloat162float(p0.x); val.y = __bfloat162float(p0.y);
            val.z = __bfloat162float(p1.x); val.w = __bfloat162float(p1.y);
        }
        *reinterpret_cast<float4*>(&vs[row][c4]) = val;
    }
    __syncthreads();
    int d = tid & 63, g = tid >> 6;
#pragma unroll 4
    for (int j = 0; j < 32; j++) {
        int n = g*32 + j;
        float s = 0.f;
#pragma unroll
        for (int k = 0; k < KW; k++) s += ws[k] * vs[n + k][d];
        g_ohf[((size_t)b*NS + n0 + n)*NI + h*64 + d] = s;
    }
}

// ---------------- host launcher ------------------------------------------------
template <typename T>
static T* symp(T& sym) { void* p = nullptr; cudaGetSymbolAddress(&p, sym); return (T*)p; }

extern "C" void kernel_launch(void* const* d_in, const int* in_sizes, int n_in,
                              void* d_out, int out_size)
{
    const float* x     = (const float*)d_in[0];
    const float* ln_g  = (const float*)d_in[1];
    const float* ln_b  = (const float*)d_in[2];
    const float* w_qkv = (const float*)d_in[3];
    const float* w_out = (const float*)d_in[4];
    const float* b_out = (const float*)d_in[5];
    const float* w_res = (const float*)d_in[6];
    float* out = (float*)d_out;

    bf16* p_xnb = symp(*g_xnb);   bf16* p_wqkvT = symp(*g_wqkvT);
    bf16* p_woutT = symp(*g_woutT);
    bf16* p_qb  = symp(*g_qb);    bf16* p_kb  = symp(*g_kb);
    bf16* p_vT  = symp(*g_vT);
    bf16* p_qlb = symp(*g_qlb);   bf16* p_klb = symp(*g_klb);
    bf16* p_a1b = symp(*g_a1b);   bf16* p_a2b = symp(*g_a2b);
    bf16* p_a3b = symp(*g_a3b);
    bf16* p_zA  = symp(*g_zA);    bf16* p_zAT = symp(*g_zAT);
    bf16* p_zB  = symp(*g_zB);    bf16* p_zBT = symp(*g_zBT);
    bf16* p_xz  = symp(*g_xz);    bf16* p_xzT = symp(*g_xzT);
    bf16* p_t1T = symp(*g_t1T);   bf16* p_t2T = symp(*g_t2T);
    bf16* p_w3T = symp(*g_w3T);   bf16* p_uT  = symp(*g_uT);
    bf16* p_ohb = symp(*g_ohb);
    float* p_s3 = symp(*g_s3);

    static bool attr_set = false;
    if (!attr_set) {
        cudaFuncSetAttribute(gemm_wmma<128>, cudaFuncAttributeMaxDynamicSharedMemorySize, DSMEM_128);
        cudaFuncSetAttribute(gemm_wmma<64>,  cudaFuncAttributeMaxDynamicSharedMemorySize, DSMEM_64);
        cudaFuncSetAttribute(gemm_pinv64, cudaFuncAttributeMaxDynamicSharedMemorySize, DSMEM_P64);
        cudaFuncSetAttribute(gemm_a3v, cudaFuncAttributeMaxDynamicSharedMemorySize, DSMEM_A3V);
        cudaFuncSetAttribute(attn_wmma, cudaFuncAttributeMaxDynamicSharedMemorySize, ATT_DSMEM);
        attr_set = true;
    }

    const long long SM2 = 65536, SW = (long long)DH*NM;

    ln_kernel<<<NB*NS, 128>>>(x, ln_g, ln_b);
    wqkvT_kernel<<<768*512/256, 256>>>(w_qkv);
    woutT_kernel<<<512*256/256, 256>>>(w_out);

    // QKV -> bf16 q/k/v (+vT)
    gemm_wmma<128><<<dim3(6, 256, 1), 256, DSMEM_128>>>(
        p_xnb, p_wqkvT, 512, 0, 0, 0, 0.f, 1.f, 1.f,
        nullptr, nullptr, nullptr, nullptr, nullptr, 0, 0);

    landmark_kernel<<<(NBH*NM*DH)/256, 256>>>(p_qb, p_qlb);
    landmark_kernel<<<(NBH*NM*DH)/256, 256>>>(p_kb, p_klb);

    // a1 = softmax(q @ kl^T), a2 = softmax(ql @ kl^T)
    attn_wmma<<<dim3(NS/64, NBH), 256, ATT_DSMEM>>>(p_qb,  p_a1b, NS);
    attn_wmma<<<dim3(NM/64, NBH), 256, ATT_DSMEM>>>(p_qlb, p_a2b, NM);

    // s3 = ql @ k^T (fp32) ; softmax -> a3 ; split-K a3@v -> w3T
    gemm_wmma<128><<<dim3(NS/128, 2, NBH), 256, DSMEM_128>>>(
        p_qlb, p_kb, 64, (long long)NM*DH, (long long)NS*DH, 5, 0.f, 1.f, 1.f,
        nullptr, nullptr, p_s3, nullptr, nullptr, (long long)NM*NS, NS);
    softmax4096_kernel<<<dim3(NM, NBH), 256>>>();
    gemm_a3v<<<dim3(SPL, 2, NBH), 256, DSMEM_A3V>>>();
    w3red_kernel<<<(NBH*NM*DH)/256, 256>>>();

    init_red_kernel<<<1, 1>>>();
    pinv_prep_kernel<<<32, 256>>>();
    zinit_kernel<<<(NBH*NM*NM)/256, 256>>>();

    bf16 *zc = p_zA, *zcT = p_zAT, *zn = p_zB, *znT = p_zBT;
    dim3 gp(2, 4, NBH);
    for (int it = 0; it < 6; it++) {
        gemm_pinv64<<<gp, 256, DSMEM_P64>>>(p_a2b, zcT, 0.f,  1.f,  1.f,   p_xz,    p_xzT);
        gemm_pinv64<<<gp, 256, DSMEM_P64>>>(p_xz, p_xzT, 7.f, -1.f,  1.f,   nullptr, p_t1T);
        gemm_pinv64<<<gp, 256, DSMEM_P64>>>(p_xz, p_t1T, 15.f, -1.f, 1.f,   nullptr, p_t2T);
        gemm_pinv64<<<gp, 256, DSMEM_P64>>>(zc,   p_t2T, 13.f, -1.f, 0.25f, zn,      znT);
        bf16* t;
        t = zc; zc = zn; zn = t;
        t = zcT; zcT = znT; znT = t;
    }
    // u^T = (z @ w3)^T
    gemm_wmma<64><<<dim3(1, 2, NBH), 256, DSMEM_64>>>(zc, p_w3T, 256, SM2, SW, 2, 0.f, 1.f, 1.f,
                                                      nullptr, p_uT, nullptr, nullptr, nullptr, 0, 0);
    // conv residual then oh = a1@u + conv
    conv_kernel<<<dim3(NS/128, NBH), 256>>>(w_res);
    gemm_wmma<64><<<dim3(1, 32, NBH), 256, DSMEM_64>>>(p_a1b, p_uT, 256, (long long)NS*NM, SW, 3,
                                                       0.f, 1.f, 1.f, nullptr, nullptr, nullptr,
                                                       nullptr, nullptr, 0, 0);
    // out = x + oh @ w_out + b
    gemm_wmma<128><<<dim3(4, 256, 1), 256, DSMEM_128>>>(p_ohb, p_woutT, 256, 0, 0, 4,
                                                        0.f, 1.f, 1.f, nullptr, nullptr, out,
                                                        b_out, x, 0, 0);
}